// round 11
// baseline (speedup 1.0000x reference)
#include <cuda_runtime.h>
#include <cuda_bf16.h>
#include <math.h>
#include <stdint.h>

// Problem constants
constexpr int kS    = 1024;
constexpr int kD    = 768;
constexpr int kL    = 12;
constexpr int kH    = 24;
constexpr int kQKV  = 2304;   // H*(32+32+32)
constexpr int kFF   = 1536;   // 2*D
constexpr int kV    = 50304;
constexpr int kK    = 768;    // shared GEMM K

// Scratch (device globals; no allocation allowed)
__device__ float g_x    [kS * kD];
__device__ float g_h    [kS * kFF];
__device__ float g_y    [kS * kQKV];
__device__ float g_state[kH * 16 * 32 * 32];
__device__ float g_zs   [kH * 16 * 32];
// pre-split bf16 activation pairs (GEMM A operands)
__device__ __nv_bfloat16 g_xh[kS * kD], g_xl[kS * kD];   // embed out
__device__ __nv_bfloat16 g_nh[kS * kD], g_nl[kS * kD];   // ln out
__device__ __nv_bfloat16 g_ah[kS * kD], g_al[kS * kD];   // attn out
__device__ __nv_bfloat16 g_gh[kS * kD], g_gl[kS * kD];   // glu out

// ================================================================ helpers
__device__ __forceinline__ uint32_t pack_split(float x, float y, float& lx, float& ly) {
    __nv_bfloat162 h = __floats2bfloat162_rn(x, y);
    lx = x - __bfloat162float(h.x);
    ly = y - __bfloat162float(h.y);
    return *reinterpret_cast<uint32_t*>(&h);
}
__device__ __forceinline__ uint32_t pack_bf2(float x, float y) {
    __nv_bfloat162 h = __floats2bfloat162_rn(x, y);
    return *reinterpret_cast<uint32_t*>(&h);
}
__device__ __forceinline__ void store_pair1(__nv_bfloat16* Hi, __nv_bfloat16* Lo,
                                            size_t idx, float v) {
    __nv_bfloat16 h = __float2bfloat16(v);
    Hi[idx] = h;
    Lo[idx] = __float2bfloat16(v - __bfloat162float(h));
}
__device__ __forceinline__ void store_pair4(__nv_bfloat16* Hi, __nv_bfloat16* Lo,
                                            size_t idx, float4 v) {
    __nv_bfloat162 h0 = __floats2bfloat162_rn(v.x, v.y);
    __nv_bfloat162 h1 = __floats2bfloat162_rn(v.z, v.w);
    __nv_bfloat162 l0 = __floats2bfloat162_rn(v.x - __bfloat162float(h0.x),
                                              v.y - __bfloat162float(h0.y));
    __nv_bfloat162 l1 = __floats2bfloat162_rn(v.z - __bfloat162float(h1.x),
                                              v.w - __bfloat162float(h1.y));
    *(__nv_bfloat162*)(Hi + idx)     = h0;
    *(__nv_bfloat162*)(Hi + idx + 2) = h1;
    *(__nv_bfloat162*)(Lo + idx)     = l0;
    *(__nv_bfloat162*)(Lo + idx + 2) = l1;
}

__device__ __forceinline__ void mma_bf16(float c[4],
                                         const uint32_t a[4],
                                         const uint32_t b[2]) {
    asm volatile(
        "mma.sync.aligned.m16n8k16.row.col.f32.bf16.bf16.f32 "
        "{%0,%1,%2,%3}, {%4,%5,%6,%7}, {%8,%9}, {%0,%1,%2,%3};"
        : "+f"(c[0]), "+f"(c[1]), "+f"(c[2]), "+f"(c[3])
        : "r"(a[0]), "r"(a[1]), "r"(a[2]), "r"(a[3]),
          "r"(b[0]), "r"(b[1]));
}
__device__ __forceinline__ void ldsm4(uint32_t r[4], uint32_t addr) {
    asm volatile("ldmatrix.sync.aligned.m8n8.x4.shared.b16 {%0,%1,%2,%3}, [%4];"
        : "=r"(r[0]), "=r"(r[1]), "=r"(r[2]), "=r"(r[3]) : "r"(addr));
}

// ================================================================ bf16-split mma GEMM
// C[M,N] = A[M,K=768] @ op(B) (+bias) (+addsrc).
// A supplied as pre-split bf16 (hi, lo). B fp32, split in-kernel.
// C = Ahi*Bhi + Ahi*Blo + Alo*Bhi.
// BM=128, BN=64, BK=16, 256 threads (8 warps, 4m x 2n), warp tile 32x32.
// smem row r at word offset r*12 (48B stride: 16B-aligned rows; 3r mod 8
// is a permutation of 0..7 -> ldmatrix conflict-free).
constexpr int kNIter = kK / 16;   // 48
constexpr int kABuf  = 1536;      // words per A buffer (128 rows x 12)
constexpr int kBBuf  = 768;       // words per B buffer (64 rows x 12)
constexpr int SAH = 0, SAL = 2 * kABuf;
constexpr int SBH = 4 * kABuf, SBL = 4 * kABuf + 2 * kBBuf;

template <bool TRANSB>
__global__ void __launch_bounds__(256, 2)
gemm_mma_kernel(const __nv_bfloat16* __restrict__ Ahi,
                const __nv_bfloat16* __restrict__ Alo,
                const float* __restrict__ B,
                const float* __restrict__ bias,
                const float* __restrict__ addsrc,
                float* __restrict__ C, int N) {
    __shared__ uint32_t sm[4 * kABuf + 4 * kBBuf];   // 36 KB

    int tid  = threadIdx.x;
    int lane = tid & 31;
    int w    = tid >> 5;
    int g    = lane >> 2;
    int t4   = lane & 3;
    int n0   = blockIdx.x * 64;
    int m0   = blockIdx.y * 128;
    int wm   = (w & 3) * 32;
    int wn   = (w >> 2) * 32;

    // ldmatrix lane addresses
    int l8 = lane & 7, quad = lane >> 3;
    int rowA0 = wm + (quad & 1) * 8 + l8;
    int offA0 = rowA0 * 12 + (quad >> 1) * 4;
    int offA1 = (rowA0 + 16) * 12 + (quad >> 1) * 4;
    int rowB0 = wn + (quad >> 1) * 8 + l8;
    int offB0 = rowB0 * 12 + (quad & 1) * 4;
    int offB2 = (rowB0 + 16) * 12 + (quad & 1) * 4;

    uint32_t su = (uint32_t)__cvta_generic_to_shared(sm);
    uint32_t aHi0 = su + (SAH + offA0) * 4, aHi1 = su + (SAH + offA1) * 4;
    uint32_t aLo0 = su + (SAL + offA0) * 4, aLo1 = su + (SAL + offA1) * 4;
    uint32_t bHi0 = su + (SBH + offB0) * 4, bHi2 = su + (SBH + offB2) * 4;
    uint32_t bLo0 = su + (SBL + offB0) * 4, bLo2 = su + (SBL + offB2) * 4;

    // ---------- staging maps
    int srow = tid >> 2;          // 0..63
    int scol = (tid & 3) * 4;     // 0,4,8,12
    const __nv_bfloat16* gAh0 = Ahi + (size_t)(m0 + srow) * kK + scol;
    const __nv_bfloat16* gAh1 = gAh0 + 64 * kK;
    const __nv_bfloat16* gAl0 = Alo + (size_t)(m0 + srow) * kK + scol;
    const __nv_bfloat16* gAl1 = gAl0 + 64 * kK;
    int wA0 = srow * 12 + (tid & 3) * 2;
    int wA1 = (srow + 64) * 12 + (tid & 3) * 2;

    const float* gBt = nullptr;
    const float* gBc = nullptr;
    int wB = 0;
    if (TRANSB) {   // 64 n-rows x 16 k-floats, same map as A rows
        gBt = B + (size_t)(n0 + srow) * kK + scol;
        wB  = srow * 12 + (tid & 3) * 2;
    } else {        // 16 k-rows x 64 n-cols
        int q = tid >> 6, nn = tid & 63;
        gBc = B + (size_t)(q * 4) * N + n0 + nn;
        wB  = nn * 12 + 2 * q;
    }

    float acc[2][4][4];
    #pragma unroll
    for (int f = 0; f < 2; f++)
        #pragma unroll
        for (int j = 0; j < 4; j++)
            #pragma unroll
            for (int u = 0; u < 4; u++) acc[f][j][u] = 0.f;

    uint2 rAh0, rAh1, rAl0, rAl1;
    float4 rb4;
    float rbn[4];

    auto ldg = [&](int it) {
        int k0 = it * 16;
        rAh0 = *(const uint2*)(gAh0 + k0);
        rAh1 = *(const uint2*)(gAh1 + k0);
        rAl0 = *(const uint2*)(gAl0 + k0);
        rAl1 = *(const uint2*)(gAl1 + k0);
        if (TRANSB) {
            rb4 = *(const float4*)(gBt + k0);
        } else {
            const float* p = gBc + (size_t)k0 * N;
            #pragma unroll
            for (int u = 0; u < 4; u++) rbn[u] = p[(size_t)u * N];
        }
    };

    auto sts = [&](int buf) {
        int boA = buf * kABuf, boB = buf * kBBuf;
        sm[SAH + boA + wA0] = rAh0.x; sm[SAH + boA + wA0 + 1] = rAh0.y;
        sm[SAH + boA + wA1] = rAh1.x; sm[SAH + boA + wA1 + 1] = rAh1.y;
        sm[SAL + boA + wA0] = rAl0.x; sm[SAL + boA + wA0 + 1] = rAl0.y;
        sm[SAL + boA + wA1] = rAl1.x; sm[SAL + boA + wA1 + 1] = rAl1.y;
        float l0, l1, l2, l3;
        if (TRANSB) {
            uint32_t h0 = pack_split(rb4.x, rb4.y, l0, l1);
            uint32_t h1 = pack_split(rb4.z, rb4.w, l2, l3);
            sm[SBH + boB + wB] = h0; sm[SBH + boB + wB + 1] = h1;
            sm[SBL + boB + wB] = pack_bf2(l0, l1);
            sm[SBL + boB + wB + 1] = pack_bf2(l2, l3);
        } else {
            uint32_t h0 = pack_split(rbn[0], rbn[1], l0, l1);
            sm[SBH + boB + wB] = h0;
            sm[SBL + boB + wB] = pack_bf2(l0, l1);
            uint32_t h1 = pack_split(rbn[2], rbn[3], l0, l1);
            sm[SBH + boB + wB + 1] = h1;
            sm[SBL + boB + wB + 1] = pack_bf2(l0, l1);
        }
    };

    ldg(0);
    sts(0);
    __syncthreads();

    for (int it = 0; it < kNIter; it++) {
        int buf = it & 1;
        uint32_t oA = (uint32_t)(buf * kABuf * 4);
        uint32_t oB = (uint32_t)(buf * kBBuf * 4);
        if (it + 1 < kNIter) ldg(it + 1);

        uint32_t ah[2][4], al[2][4], bq0[4], bq2[4], lq0[4], lq2[4];
        ldsm4(ah[0], aHi0 + oA);
        ldsm4(ah[1], aHi1 + oA);
        ldsm4(al[0], aLo0 + oA);
        ldsm4(al[1], aLo1 + oA);
        ldsm4(bq0, bHi0 + oB);
        ldsm4(bq2, bHi2 + oB);
        ldsm4(lq0, bLo0 + oB);
        ldsm4(lq2, bLo2 + oB);

        uint32_t bh[4][2] = {{bq0[0], bq0[1]}, {bq0[2], bq0[3]},
                             {bq2[0], bq2[1]}, {bq2[2], bq2[3]}};
        uint32_t bl[4][2] = {{lq0[0], lq0[1]}, {lq0[2], lq0[3]},
                             {lq2[0], lq2[1]}, {lq2[2], lq2[3]}};

        #pragma unroll
        for (int f = 0; f < 2; f++)
            #pragma unroll
            for (int j = 0; j < 4; j++) {
                mma_bf16(acc[f][j], ah[f], bh[j]);
                mma_bf16(acc[f][j], ah[f], bl[j]);
                mma_bf16(acc[f][j], al[f], bh[j]);
            }

        if (it + 1 < kNIter) sts(buf ^ 1);
        __syncthreads();
    }

    // epilogue
    #pragma unroll
    for (int f = 0; f < 2; f++) {
        int r0 = m0 + wm + f * 16 + g;
        #pragma unroll
        for (int j = 0; j < 4; j++) {
            int n = n0 + wn + j * 8 + t4 * 2;
            float2 lo = {acc[f][j][0], acc[f][j][1]};
            float2 hi = {acc[f][j][2], acc[f][j][3]};
            if (bias) {
                float2 b2 = *(const float2*)(bias + n);
                lo.x += b2.x; lo.y += b2.y;
                hi.x += b2.x; hi.y += b2.y;
            }
            size_t o0 = (size_t)r0 * N + n;
            size_t o1 = (size_t)(r0 + 8) * N + n;
            if (addsrc) {
                float2 s0 = *(const float2*)(addsrc + o0);
                float2 s1 = *(const float2*)(addsrc + o1);
                lo.x += s0.x; lo.y += s0.y;
                hi.x += s1.x; hi.y += s1.y;
            }
            *(float2*)(C + o0) = lo;
            *(float2*)(C + o1) = hi;
        }
    }
}

// ================================================================ embed gather (float4 + pairs)
__global__ void embed_kernel(const int* __restrict__ tok,
                             const float* __restrict__ ew,
                             float* __restrict__ x,
                             __nv_bfloat16* __restrict__ xh,
                             __nv_bfloat16* __restrict__ xl) {
    int idx = blockIdx.x * blockDim.x + threadIdx.x;
    if (idx < kS * (kD / 4)) {
        int t = idx / 192, d4 = idx - t * 192;
        float4 v = *(const float4*)(ew + (size_t)tok[t] * kD + d4 * 4);
        size_t o = (size_t)t * kD + d4 * 4;
        *(float4*)(x + o) = v;
        store_pair4(xh, xl, o, v);
    }
}

// ================================================================ layernorm -> bf16 pairs
__global__ void ln_kernel(const float* __restrict__ x,
                          const float* __restrict__ gw,
                          const float* __restrict__ bw,
                          __nv_bfloat16* __restrict__ oh,
                          __nv_bfloat16* __restrict__ ol) {
    int row = blockIdx.x;
    int tid = threadIdx.x;  // 256
    const float* xr = x + (size_t)row * kD;
    float v0 = xr[tid], v1 = xr[tid + 256], v2 = xr[tid + 512];
    float s = v0 + v1 + v2;
    __shared__ float red[8];
    unsigned lane = tid & 31, wid = tid >> 5;
    #pragma unroll
    for (int o = 16; o > 0; o >>= 1) s += __shfl_down_sync(0xffffffffu, s, o);
    if (lane == 0) red[wid] = s;
    __syncthreads();
    float tot = 0.f;
    #pragma unroll
    for (int i = 0; i < 8; i++) tot += red[i];
    float m = tot * (1.f / 768.f);
    float d0 = v0 - m, d1 = v1 - m, d2 = v2 - m;
    float s2 = d0 * d0 + d1 * d1 + d2 * d2;
    __syncthreads();
    #pragma unroll
    for (int o = 16; o > 0; o >>= 1) s2 += __shfl_down_sync(0xffffffffu, s2, o);
    if (lane == 0) red[wid] = s2;
    __syncthreads();
    float tot2 = 0.f;
    #pragma unroll
    for (int i = 0; i < 8; i++) tot2 += red[i];
    float scale = rsqrtf(tot2 * (1.f / 768.f) + 1e-5f);
    size_t base = (size_t)row * kD;
    store_pair1(oh, ol, base + tid,       d0 * scale * gw[tid]       + bw[tid]);
    store_pair1(oh, ol, base + tid + 256, d1 * scale * gw[tid + 256] + bw[tid + 256]);
    store_pair1(oh, ol, base + tid + 512, d2 * scale * gw[tid + 512] + bw[tid + 512]);
}

// ================================================================ pos scan
__global__ void pos_scan_kernel(const float* __restrict__ h, float* __restrict__ x) {
    int d = blockIdx.x * blockDim.x + threadIdx.x;
    if (d >= kD) return;
    float a = 0.f, Lv = 0.f;
    for (int t = 0; t < kS; t++) {
        float hc = h[(size_t)t * kFF + d];
        float hl = h[(size_t)t * kFF + kD + d];
        float lc = fminf(hc, 0.f) - log1pf(__expf(-fabsf(hc)));
        a += lc;
        float v = hl - a;
        float mx = fmaxf(Lv, v), mn = fminf(Lv, v);
        Lv = mx + log1pf(__expf(mn - mx));
        x[(size_t)t * kD + d] += a + Lv;
    }
}

// ================================================================ GLU -> bf16 pairs
__global__ void glu_kernel(const float* __restrict__ z,
                           __nv_bfloat16* __restrict__ gh,
                           __nv_bfloat16* __restrict__ gl) {
    int idx = blockIdx.x * blockDim.x + threadIdx.x;
    if (idx < kS * (kD / 4)) {
        int t = idx / 192, d4 = idx - t * 192;
        float4 a = *(const float4*)(z + (size_t)t * kFF + d4 * 4);
        float4 b = *(const float4*)(z + (size_t)t * kFF + kD + d4 * 4);
        float4 o;
        o.x = a.x / (1.f + __expf(-b.x));
        o.y = a.y / (1.f + __expf(-b.y));
        o.z = a.z / (1.f + __expf(-b.z));
        o.w = a.w / (1.f + __expf(-b.w));
        store_pair4(gh, gl, (size_t)t * kD + d4 * 4, o);
    }
}

// ================================================================ chunked attention
__global__ void __launch_bounds__(256)
attn_state_kernel(const float* __restrict__ y, float* __restrict__ state,
                  float* __restrict__ zs) {
    __shared__ float sK[64][36];
    __shared__ float sV[64][36];
    int t = blockIdx.x, h = blockIdx.y;
    int tid = threadIdx.x;
    int i4 = (tid & 7) * 4, rr = tid >> 3;
    #pragma unroll
    for (int rep = 0; rep < 2; rep++) {
        int s = rr + rep * 32;
        const float* base = y + (size_t)(t * 64 + s) * kQKV + h * 96;
        float4 kv = *(const float4*)(base + 32 + i4);
        float4 vv = *(const float4*)(base + 64 + i4);
        float4 ek = {__expf(kv.x), __expf(kv.y), __expf(kv.z), __expf(kv.w)};
        float4 ev = {__expf(vv.x), __expf(vv.y), __expf(vv.z), __expf(vv.w)};
        *(float4*)&sK[s][i4] = ek;
        *(float4*)&sV[s][i4] = ev;
    }
    __syncthreads();
    int i = tid >> 3, j0 = (tid & 7) * 4;
    float a0 = 0.f, a1 = 0.f, a2 = 0.f, a3 = 0.f;
    #pragma unroll 4
    for (int s = 0; s < 64; s++) {
        float k = sK[s][i];
        float4 v = *(float4*)&sV[s][j0];
        a0 += k * v.x; a1 += k * v.y; a2 += k * v.z; a3 += k * v.w;
    }
    float4 o = {a0, a1, a2, a3};
    *(float4*)&state[((size_t)(h * 16 + t) * 32 + i) * 32 + j0] = o;
    if (tid < 32) {
        float z = 0.f;
        #pragma unroll 4
        for (int s = 0; s < 64; s++) z += sK[s][tid];
        zs[(h * 16 + t) * 32 + tid] = z;
    }
}

__global__ void __launch_bounds__(1024)
attn_prefix_kernel(float* __restrict__ state, float* __restrict__ zs) {
    int h = blockIdx.x;
    int idx = threadIdx.x;
    float v[16];
    #pragma unroll
    for (int t = 0; t < 16; t++)
        v[t] = state[(size_t)(h * 16 + t) * 1024 + idx];
    float run = 0.f;
    #pragma unroll
    for (int t = 0; t < 16; t++) {
        state[(size_t)(h * 16 + t) * 1024 + idx] = run;
        run += v[t];
    }
    if (idx < 32) {
        float zv[16];
        #pragma unroll
        for (int t = 0; t < 16; t++) zv[t] = zs[(h * 16 + t) * 32 + idx];
        float rz = 0.f;
        #pragma unroll
        for (int t = 0; t < 16; t++) {
            zs[(h * 16 + t) * 32 + idx] = rz;
            rz += zv[t];
        }
    }
}

__global__ void __launch_bounds__(256)
attn_out_kernel(const float* __restrict__ y, const float* __restrict__ state,
                const float* __restrict__ zs,
                __nv_bfloat16* __restrict__ ah, __nv_bfloat16* __restrict__ al) {
    __shared__ float sQ[32][64];
    __shared__ float sK[32][64];
    __shared__ float sV[64][36];
    __shared__ float sSt[32][36];
    __shared__ float sZp[32];
    __shared__ float sP[64][65];
    __shared__ float sZ[64];

    int qt = blockIdx.x, h = blockIdx.y;
    int t0 = qt * 64;
    int tid = threadIdx.x;
    int i4 = (tid & 7) * 4, rr = tid >> 3;

    #pragma unroll
    for (int rep = 0; rep < 2; rep++) {
        int s = rr + rep * 32;
        const float* base = y + (size_t)(t0 + s) * kQKV + h * 96;
        float4 qv = *(const float4*)(base + i4);
        sQ[i4 + 0][s] = __expf(qv.x); sQ[i4 + 1][s] = __expf(qv.y);
        sQ[i4 + 2][s] = __expf(qv.z); sQ[i4 + 3][s] = __expf(qv.w);
        float4 kv = *(const float4*)(base + 32 + i4);
        sK[i4 + 0][s] = __expf(kv.x); sK[i4 + 1][s] = __expf(kv.y);
        sK[i4 + 2][s] = __expf(kv.z); sK[i4 + 3][s] = __expf(kv.w);
        float4 vv = *(const float4*)(base + 64 + i4);
        float4 ev = {__expf(vv.x), __expf(vv.y), __expf(vv.z), __expf(vv.w)};
        *(float4*)&sV[s][i4] = ev;
    }
    {
        int i = tid >> 3, j0 = (tid & 7) * 4;
        float4 st = *(const float4*)&state[((size_t)(h * 16 + qt) * 32 + i) * 32 + j0];
        *(float4*)&sSt[i][j0] = st;
        if (tid < 32) sZp[tid] = zs[(h * 16 + qt) * 32 + tid];
    }
    __syncthreads();

    int tk = tid & 15, tq = tid >> 4;
    {
        float p[4][4] = {};
        #pragma unroll
        for (int i = 0; i < 32; i++) {
            float4 a4 = *(float4*)&sQ[i][tq * 4];
            float4 b4 = *(float4*)&sK[i][tk * 4];
            float ar[4] = {a4.x, a4.y, a4.z, a4.w};
            float br[4] = {b4.x, b4.y, b4.z, b4.w};
            #pragma unroll
            for (int r = 0; r < 4; r++)
                #pragma unroll
                for (int c = 0; c < 4; c++)
                    p[r][c] += ar[r] * br[c];
        }
        #pragma unroll
        for (int r = 0; r < 4; r++)
            #pragma unroll
            for (int c = 0; c < 4; c++)
                sP[tq * 4 + r][tk * 4 + c] =
                    (tk * 4 + c > tq * 4 + r) ? 0.f : p[r][c];
    }
    __syncthreads();

    int vx = tid & 7, ry = tid >> 3;
    float Sacc[2][4] = {};
    float Zacc[2] = {};
    {
        #pragma unroll 4
        for (int i = 0; i < 32; i++) {
            float q0 = sQ[i][ry * 2 + 0];
            float q1 = sQ[i][ry * 2 + 1];
            float4 st = *(float4*)&sSt[i][vx * 4];
            Sacc[0][0] += q0 * st.x; Sacc[0][1] += q0 * st.y;
            Sacc[0][2] += q0 * st.z; Sacc[0][3] += q0 * st.w;
            Sacc[1][0] += q1 * st.x; Sacc[1][1] += q1 * st.y;
            Sacc[1][2] += q1 * st.z; Sacc[1][3] += q1 * st.w;
            if (vx == 0) {
                float z = sZp[i];
                Zacc[0] += q0 * z; Zacc[1] += q1 * z;
            }
        }
        #pragma unroll 8
        for (int s = 0; s < 64; s++) {
            float p0 = sP[ry * 2 + 0][s];
            float p1 = sP[ry * 2 + 1][s];
            float4 vv = *(float4*)&sV[s][vx * 4];
            Sacc[0][0] += p0 * vv.x; Sacc[0][1] += p0 * vv.y;
            Sacc[0][2] += p0 * vv.z; Sacc[0][3] += p0 * vv.w;
            Sacc[1][0] += p1 * vv.x; Sacc[1][1] += p1 * vv.y;
            Sacc[1][2] += p1 * vv.z; Sacc[1][3] += p1 * vv.w;
            if (vx == 0) { Zacc[0] += p0; Zacc[1] += p1; }
        }
    }
    if (vx == 0) { sZ[ry * 2] = Zacc[0]; sZ[ry * 2 + 1] = Zacc[1]; }
    __syncthreads();
    #pragma unroll
    for (int r = 0; r < 2; r++) {
        int row = t0 + ry * 2 + r;
        float lz = __logf(sZ[ry * 2 + r]);
        float4 o;
        o.x = __logf(Sacc[r][0]) - lz;
        o.y = __logf(Sacc[r][1]) - lz;
        o.z = __logf(Sacc[r][2]) - lz;
        o.w = __logf(Sacc[r][3]) - lz;
        store_pair4(ah, al, (size_t)row * kD + h * 32 + vx * 4, o);
    }
}

// ================================================================ launch
extern "C" void kernel_launch(void* const* d_in, const int* in_sizes, int n_in,
                              void* d_out, int out_size) {
    const int*   tok     = (const int*)  d_in[0];
    const float* embed_w = (const float*)d_in[1];
    const float* pos_w   = (const float*)d_in[2];
    const float* pos_b   = (const float*)d_in[3];
    const float* ln1_g   = (const float*)d_in[4];
    const float* ln1_b   = (const float*)d_in[5];
    const float* qkv_w   = (const float*)d_in[6];
    const float* qkv_b   = (const float*)d_in[7];
    const float* ff_w1   = (const float*)d_in[8];
    const float* ff_b1   = (const float*)d_in[9];
    const float* ff_w2   = (const float*)d_in[10];
    const float* lnf_g   = (const float*)d_in[11];
    const float* lnf_b   = (const float*)d_in[12];
    float* out = (float*)d_out;

    float *x, *hbuf, *y, *st, *zsb;
    __nv_bfloat16 *xh, *xl, *nh, *nl, *ah, *al, *gh, *gl;
    cudaGetSymbolAddress((void**)&x,    g_x);
    cudaGetSymbolAddress((void**)&hbuf, g_h);
    cudaGetSymbolAddress((void**)&y,    g_y);
    cudaGetSymbolAddress((void**)&st,   g_state);
    cudaGetSymbolAddress((void**)&zsb,  g_zs);
    cudaGetSymbolAddress((void**)&xh,   g_xh);
    cudaGetSymbolAddress((void**)&xl,   g_xl);
    cudaGetSymbolAddress((void**)&nh,   g_nh);
    cudaGetSymbolAddress((void**)&nl,   g_nl);
    cudaGetSymbolAddress((void**)&ah,   g_ah);
    cudaGetSymbolAddress((void**)&al,   g_al);
    cudaGetSymbolAddress((void**)&gh,   g_gh);
    cudaGetSymbolAddress((void**)&gl,   g_gl);

    // 1. embedding (fp32 + pairs)
    embed_kernel<<<(kS * 192 + 255) / 256, 256>>>(tok, embed_w, x, xh, xl);

    // 2. positional
    gemm_mma_kernel<false><<<dim3(kFF / 64, kS / 128), 256>>>(
        xh, xl, pos_w, pos_b, nullptr, hbuf, kFF);
    pos_scan_kernel<<<6, 128>>>(hbuf, x);

    // 3. layers
    for (int l = 0; l < kL; l++) {
        ln_kernel<<<kS, 256>>>(x, ln1_g + (size_t)l * kD, ln1_b + (size_t)l * kD, nh, nl);
        gemm_mma_kernel<false><<<dim3(kQKV / 64, kS / 128), 256>>>(
            nh, nl, qkv_w + (size_t)l * kD * kQKV, qkv_b + (size_t)l * kQKV,
            nullptr, y, kQKV);
        attn_state_kernel<<<dim3(16, kH), 256>>>(y, st, zsb);
        attn_prefix_kernel<<<kH, 1024>>>(st, zsb);
        attn_out_kernel<<<dim3(16, kH), 256>>>(y, st, zsb, ah, al);
        gemm_mma_kernel<false><<<dim3(kFF / 64, kS / 128), 256>>>(
            ah, al, ff_w1 + (size_t)l * kD * kFF, ff_b1 + (size_t)l * kFF,
            nullptr, hbuf, kFF);
        glu_kernel<<<(kS * 192 + 255) / 256, 256>>>(hbuf, gh, gl);
        gemm_mma_kernel<false><<<dim3(kD / 64, kS / 128), 256>>>(
            gh, gl, ff_w2 + (size_t)l * kD * kD, nullptr, x, x, kD);
    }

    // 4. final LN + logits (BN=64 TRANSB vs embed table — r9-proven shape)
    ln_kernel<<<kS, 256>>>(x, lnf_g, lnf_b, nh, nl);
    gemm_mma_kernel<true><<<dim3(kV / 64, kS / 128), 256>>>(
        nh, nl, embed_w, nullptr, nullptr, out, kV);
}

// round 12
// speedup vs baseline: 1.9063x; 1.9063x over previous
#include <cuda_runtime.h>
#include <cuda_fp16.h>
#include <math.h>
#include <stdint.h>

// Problem constants
constexpr int kS    = 1024;
constexpr int kD    = 768;
constexpr int kL    = 12;
constexpr int kH    = 24;
constexpr int kQKV  = 2304;   // H*(32+32+32)
constexpr int kFF   = 1536;   // 2*D
constexpr int kV    = 50304;
constexpr int kK    = 768;    // shared GEMM K

// Scratch (device globals; no allocation allowed)
__device__ float g_x    [kS * kD];
__device__ float g_xn   [kS * kD];
__device__ float g_h    [kS * kFF];
__device__ float g_y    [kS * kQKV];
__device__ float g_att  [kS * kD];
__device__ float g_g    [kS * kD];
__device__ float g_state[kH * 16 * 32 * 32];
__device__ float g_zs   [kH * 16 * 32];

// ================================================================ fp16-split mma GEMM
// C[M,N] = A[M,K=768] @ op(B) (+bias) (+addsrc), fp32 in/out.
// A = Ahi + Alo (fp16 pair, in-kernel split; A-side error ~2^-24).
// B -> Bhi only (fp16 rn; the dropped residual gives ~1e-4 rel err, within budget).
// C = Ahi*Bhi + Alo*Bhi  -> 2 MMAs per (f,j) per k16 instead of 3.
// BM=128, BN=64, BK=16, 256 threads (8 warps, 4m x 2n), warp tile 32x32.
// Fragments via ldmatrix.x4; smem row r at word offset r*12 (48B stride:
// 16B-aligned rows; 3r mod 8 is a permutation -> ldmatrix conflict-free).
constexpr int kNIter = kK / 16;   // 48
constexpr int kABuf  = 1536;      // words per A plane buffer (128 rows x 12)
constexpr int kBBuf  = 768;       // words per B plane buffer (64 rows x 12)
constexpr int SAH = 0;                    // A hi: 2 bufs
constexpr int SAL = 2 * kABuf;            // A lo: 2 bufs
constexpr int SBH = 4 * kABuf;            // B hi: 2 bufs
constexpr int kSmWords = 4 * kABuf + 2 * kBBuf;   // 7680 words = 30 KB

__device__ __forceinline__ uint32_t pack_h2_split(float x, float y, float& lx, float& ly) {
    __half2 h = __floats2half2_rn(x, y);
    lx = x - __low2float(h);
    ly = y - __high2float(h);
    return *reinterpret_cast<uint32_t*>(&h);
}
__device__ __forceinline__ uint32_t pack_h2(float x, float y) {
    __half2 h = __floats2half2_rn(x, y);
    return *reinterpret_cast<uint32_t*>(&h);
}

__device__ __forceinline__ void mma_fp16(float c[4],
                                         const uint32_t a[4],
                                         const uint32_t b[2]) {
    asm volatile(
        "mma.sync.aligned.m16n8k16.row.col.f32.f16.f16.f32 "
        "{%0,%1,%2,%3}, {%4,%5,%6,%7}, {%8,%9}, {%0,%1,%2,%3};"
        : "+f"(c[0]), "+f"(c[1]), "+f"(c[2]), "+f"(c[3])
        : "r"(a[0]), "r"(a[1]), "r"(a[2]), "r"(a[3]),
          "r"(b[0]), "r"(b[1]));
}
__device__ __forceinline__ void ldsm4(uint32_t r[4], uint32_t addr) {
    asm volatile("ldmatrix.sync.aligned.m8n8.x4.shared.b16 {%0,%1,%2,%3}, [%4];"
        : "=r"(r[0]), "=r"(r[1]), "=r"(r[2]), "=r"(r[3]) : "r"(addr));
}

template <bool TRANSB>
__global__ void __launch_bounds__(256, 2)
gemm_mma_kernel(const float* __restrict__ A, const float* __restrict__ B,
                const float* __restrict__ bias, const float* __restrict__ addsrc,
                float* __restrict__ C, int N) {
    __shared__ uint32_t sm[kSmWords];

    int tid  = threadIdx.x;
    int lane = tid & 31;
    int w    = tid >> 5;
    int g    = lane >> 2;
    int t4   = lane & 3;
    int n0   = blockIdx.x * 64;
    int m0   = blockIdx.y * 128;
    int wm   = (w & 3) * 32;
    int wn   = (w >> 2) * 32;

    // ldmatrix lane addresses (loop-invariant word offsets)
    int l8 = lane & 7, quad = lane >> 3;
    int rowA0 = wm + (quad & 1) * 8 + l8;
    int offA0 = rowA0 * 12 + (quad >> 1) * 4;
    int offA1 = (rowA0 + 16) * 12 + (quad >> 1) * 4;
    int rowB0 = wn + (quad >> 1) * 8 + l8;
    int offB0 = rowB0 * 12 + (quad & 1) * 4;
    int offB2 = (rowB0 + 16) * 12 + (quad & 1) * 4;

    uint32_t su = (uint32_t)__cvta_generic_to_shared(sm);
    uint32_t aHi0 = su + (SAH + offA0) * 4, aHi1 = su + (SAH + offA1) * 4;
    uint32_t aLo0 = su + (SAL + offA0) * 4, aLo1 = su + (SAL + offA1) * 4;
    uint32_t bHi0 = su + (SBH + offB0) * 4, bHi2 = su + (SBH + offB2) * 4;

    // ---------- staging maps (identical structure to the proven r9 kernel)
    int srow = tid >> 2;          // 0..63
    int scol = (tid & 3) * 4;     // 0,4,8,12
    const float* gA0 = A + (size_t)(m0 + srow) * kK + scol;
    const float* gA1 = A + (size_t)(m0 + srow + 64) * kK + scol;
    int wA0 = srow * 12 + (tid & 3) * 2;
    int wA1 = (srow + 64) * 12 + (tid & 3) * 2;

    const float* gBt = nullptr;
    const float* gBc = nullptr;
    int wB = 0;
    if (TRANSB) {
        gBt = B + (size_t)(n0 + srow) * kK + scol;
        wB  = srow * 12 + (tid & 3) * 2;
    } else {
        int q = tid >> 6, nn = tid & 63;
        gBc = B + (size_t)(q * 4) * N + n0 + nn;
        wB  = nn * 12 + 2 * q;
    }

    float acc[2][4][4];
    #pragma unroll
    for (int f = 0; f < 2; f++)
        #pragma unroll
        for (int j = 0; j < 4; j++)
            #pragma unroll
            for (int u = 0; u < 4; u++) acc[f][j][u] = 0.f;

    float4 ra0, ra1, rb4;
    float rbn[4];

    auto ldg = [&](int it) {
        int k0 = it * 16;
        ra0 = *(const float4*)(gA0 + k0);
        ra1 = *(const float4*)(gA1 + k0);
        if (TRANSB) {
            rb4 = *(const float4*)(gBt + k0);
        } else {
            const float* p = gBc + (size_t)k0 * N;
            #pragma unroll
            for (int u = 0; u < 4; u++) rbn[u] = p[(size_t)u * N];
        }
    };

    auto sts = [&](int buf) {
        int boA = buf * kABuf, boB = buf * kBBuf;
        float l0, l1, l2, l3;
        uint32_t h0 = pack_h2_split(ra0.x, ra0.y, l0, l1);
        uint32_t h1 = pack_h2_split(ra0.z, ra0.w, l2, l3);
        sm[SAH + boA + wA0] = h0; sm[SAH + boA + wA0 + 1] = h1;
        sm[SAL + boA + wA0] = pack_h2(l0, l1);
        sm[SAL + boA + wA0 + 1] = pack_h2(l2, l3);
        h0 = pack_h2_split(ra1.x, ra1.y, l0, l1);
        h1 = pack_h2_split(ra1.z, ra1.w, l2, l3);
        sm[SAH + boA + wA1] = h0; sm[SAH + boA + wA1 + 1] = h1;
        sm[SAL + boA + wA1] = pack_h2(l0, l1);
        sm[SAL + boA + wA1 + 1] = pack_h2(l2, l3);
        if (TRANSB) {
            sm[SBH + boB + wB]     = pack_h2(rb4.x, rb4.y);
            sm[SBH + boB + wB + 1] = pack_h2(rb4.z, rb4.w);
        } else {
            sm[SBH + boB + wB]     = pack_h2(rbn[0], rbn[1]);
            sm[SBH + boB + wB + 1] = pack_h2(rbn[2], rbn[3]);
        }
    };

    ldg(0);
    sts(0);
    __syncthreads();

    for (int it = 0; it < kNIter; it++) {
        int buf = it & 1;
        uint32_t oA = (uint32_t)(buf * kABuf * 4);
        uint32_t oB = (uint32_t)(buf * kBBuf * 4);
        if (it + 1 < kNIter) ldg(it + 1);

        uint32_t ah[2][4], al[2][4], bq0[4], bq2[4];
        ldsm4(ah[0], aHi0 + oA);
        ldsm4(ah[1], aHi1 + oA);
        ldsm4(al[0], aLo0 + oA);
        ldsm4(al[1], aLo1 + oA);
        ldsm4(bq0, bHi0 + oB);
        ldsm4(bq2, bHi2 + oB);

        uint32_t bh[4][2] = {{bq0[0], bq0[1]}, {bq0[2], bq0[3]},
                             {bq2[0], bq2[1]}, {bq2[2], bq2[3]}};

        #pragma unroll
        for (int f = 0; f < 2; f++)
            #pragma unroll
            for (int j = 0; j < 4; j++) {
                mma_fp16(acc[f][j], ah[f], bh[j]);
                mma_fp16(acc[f][j], al[f], bh[j]);
            }

        if (it + 1 < kNIter) sts(buf ^ 1);
        __syncthreads();
    }

    // epilogue
    #pragma unroll
    for (int f = 0; f < 2; f++) {
        int r0 = m0 + wm + f * 16 + g;
        #pragma unroll
        for (int j = 0; j < 4; j++) {
            int n = n0 + wn + j * 8 + t4 * 2;
            float2 lo = {acc[f][j][0], acc[f][j][1]};
            float2 hi = {acc[f][j][2], acc[f][j][3]};
            if (bias) {
                float2 b2 = *(const float2*)(bias + n);
                lo.x += b2.x; lo.y += b2.y;
                hi.x += b2.x; hi.y += b2.y;
            }
            size_t o0 = (size_t)r0 * N + n;
            size_t o1 = (size_t)(r0 + 8) * N + n;
            if (addsrc) {
                float2 s0 = *(const float2*)(addsrc + o0);
                float2 s1 = *(const float2*)(addsrc + o1);
                lo.x += s0.x; lo.y += s0.y;
                hi.x += s1.x; hi.y += s1.y;
            }
            *(float2*)(C + o0) = lo;
            *(float2*)(C + o1) = hi;
        }
    }
}

// ================================================================ embed gather (float4)
__global__ void embed_kernel(const int* __restrict__ tok,
                             const float* __restrict__ ew,
                             float* __restrict__ x) {
    int idx = blockIdx.x * blockDim.x + threadIdx.x;
    if (idx < kS * (kD / 4)) {
        int t = idx / 192, d4 = idx - t * 192;
        float4 v = *(const float4*)(ew + (size_t)tok[t] * kD + d4 * 4);
        *(float4*)(x + (size_t)t * kD + d4 * 4) = v;
    }
}

// ================================================================ layernorm
__global__ void ln_kernel(const float* __restrict__ x,
                          const float* __restrict__ gw,
                          const float* __restrict__ bw,
                          float* __restrict__ out) {
    int row = blockIdx.x;
    int tid = threadIdx.x;  // 256
    const float* xr = x + (size_t)row * kD;
    float v0 = xr[tid], v1 = xr[tid + 256], v2 = xr[tid + 512];
    float s = v0 + v1 + v2;
    __shared__ float red[8];
    unsigned lane = tid & 31, wid = tid >> 5;
    #pragma unroll
    for (int o = 16; o > 0; o >>= 1) s += __shfl_down_sync(0xffffffffu, s, o);
    if (lane == 0) red[wid] = s;
    __syncthreads();
    float tot = 0.f;
    #pragma unroll
    for (int i = 0; i < 8; i++) tot += red[i];
    float m = tot * (1.f / 768.f);
    float d0 = v0 - m, d1 = v1 - m, d2 = v2 - m;
    float s2 = d0 * d0 + d1 * d1 + d2 * d2;
    __syncthreads();
    #pragma unroll
    for (int o = 16; o > 0; o >>= 1) s2 += __shfl_down_sync(0xffffffffu, s2, o);
    if (lane == 0) red[wid] = s2;
    __syncthreads();
    float tot2 = 0.f;
    #pragma unroll
    for (int i = 0; i < 8; i++) tot2 += red[i];
    float scale = rsqrtf(tot2 * (1.f / 768.f) + 1e-5f);
    float* orow = out + (size_t)row * kD;
    orow[tid]       = d0 * scale * gw[tid]       + bw[tid];
    orow[tid + 256] = d1 * scale * gw[tid + 256] + bw[tid + 256];
    orow[tid + 512] = d2 * scale * gw[tid + 512] + bw[tid + 512];
}

// ================================================================ pos scan
__global__ void pos_scan_kernel(const float* __restrict__ h, float* __restrict__ x) {
    int d = blockIdx.x * blockDim.x + threadIdx.x;
    if (d >= kD) return;
    float a = 0.f, Lv = 0.f;
    for (int t = 0; t < kS; t++) {
        float hc = h[(size_t)t * kFF + d];
        float hl = h[(size_t)t * kFF + kD + d];
        float lc = fminf(hc, 0.f) - log1pf(__expf(-fabsf(hc)));
        a += lc;
        float v = hl - a;
        float mx = fmaxf(Lv, v), mn = fminf(Lv, v);
        Lv = mx + log1pf(__expf(mn - mx));
        x[(size_t)t * kD + d] += a + Lv;
    }
}

// ================================================================ GLU (float4)
__global__ void glu_kernel(const float* __restrict__ z, float* __restrict__ g) {
    int idx = blockIdx.x * blockDim.x + threadIdx.x;
    if (idx < kS * (kD / 4)) {
        int t = idx / 192, d4 = idx - t * 192;
        float4 a = *(const float4*)(z + (size_t)t * kFF + d4 * 4);
        float4 b = *(const float4*)(z + (size_t)t * kFF + kD + d4 * 4);
        float4 o;
        o.x = a.x / (1.f + __expf(-b.x));
        o.y = a.y / (1.f + __expf(-b.y));
        o.z = a.z / (1.f + __expf(-b.z));
        o.w = a.w / (1.f + __expf(-b.w));
        *(float4*)(g + (size_t)t * kD + d4 * 4) = o;
    }
}

// ================================================================ chunked attention
__global__ void __launch_bounds__(256)
attn_state_kernel(const float* __restrict__ y, float* __restrict__ state,
                  float* __restrict__ zs) {
    __shared__ float sK[64][36];
    __shared__ float sV[64][36];
    int t = blockIdx.x, h = blockIdx.y;
    int tid = threadIdx.x;
    int i4 = (tid & 7) * 4, rr = tid >> 3;
    #pragma unroll
    for (int rep = 0; rep < 2; rep++) {
        int s = rr + rep * 32;
        const float* base = y + (size_t)(t * 64 + s) * kQKV + h * 96;
        float4 kv = *(const float4*)(base + 32 + i4);
        float4 vv = *(const float4*)(base + 64 + i4);
        float4 ek = {__expf(kv.x), __expf(kv.y), __expf(kv.z), __expf(kv.w)};
        float4 ev = {__expf(vv.x), __expf(vv.y), __expf(vv.z), __expf(vv.w)};
        *(float4*)&sK[s][i4] = ek;
        *(float4*)&sV[s][i4] = ev;
    }
    __syncthreads();
    int i = tid >> 3, j0 = (tid & 7) * 4;
    float a0 = 0.f, a1 = 0.f, a2 = 0.f, a3 = 0.f;
    #pragma unroll 4
    for (int s = 0; s < 64; s++) {
        float k = sK[s][i];
        float4 v = *(float4*)&sV[s][j0];
        a0 += k * v.x; a1 += k * v.y; a2 += k * v.z; a3 += k * v.w;
    }
    float4 o = {a0, a1, a2, a3};
    *(float4*)&state[((size_t)(h * 16 + t) * 32 + i) * 32 + j0] = o;
    if (tid < 32) {
        float z = 0.f;
        #pragma unroll 4
        for (int s = 0; s < 64; s++) z += sK[s][tid];
        zs[(h * 16 + t) * 32 + tid] = z;
    }
}

// prefix over 16 tiles (prefetch then scan)
__global__ void __launch_bounds__(1024)
attn_prefix_kernel(float* __restrict__ state, float* __restrict__ zs) {
    int h = blockIdx.x;
    int idx = threadIdx.x;
    float v[16];
    #pragma unroll
    for (int t = 0; t < 16; t++)
        v[t] = state[(size_t)(h * 16 + t) * 1024 + idx];
    float run = 0.f;
    #pragma unroll
    for (int t = 0; t < 16; t++) {
        state[(size_t)(h * 16 + t) * 1024 + idx] = run;
        run += v[t];
    }
    if (idx < 32) {
        float zv[16];
        #pragma unroll
        for (int t = 0; t < 16; t++) zv[t] = zs[(h * 16 + t) * 32 + idx];
        float rz = 0.f;
        #pragma unroll
        for (int t = 0; t < 16; t++) {
            zs[(h * 16 + t) * 32 + idx] = rz;
            rz += zv[t];
        }
    }
}

__global__ void __launch_bounds__(256)
attn_out_kernel(const float* __restrict__ y, const float* __restrict__ state,
                const float* __restrict__ zs, float* __restrict__ att) {
    __shared__ float sQ[32][64];
    __shared__ float sK[32][64];
    __shared__ float sV[64][36];
    __shared__ float sSt[32][36];
    __shared__ float sZp[32];
    __shared__ float sP[64][65];
    __shared__ float sZ[64];

    int qt = blockIdx.x, h = blockIdx.y;
    int t0 = qt * 64;
    int tid = threadIdx.x;
    int i4 = (tid & 7) * 4, rr = tid >> 3;

    #pragma unroll
    for (int rep = 0; rep < 2; rep++) {
        int s = rr + rep * 32;
        const float* base = y + (size_t)(t0 + s) * kQKV + h * 96;
        float4 qv = *(const float4*)(base + i4);
        sQ[i4 + 0][s] = __expf(qv.x); sQ[i4 + 1][s] = __expf(qv.y);
        sQ[i4 + 2][s] = __expf(qv.z); sQ[i4 + 3][s] = __expf(qv.w);
        float4 kv = *(const float4*)(base + 32 + i4);
        sK[i4 + 0][s] = __expf(kv.x); sK[i4 + 1][s] = __expf(kv.y);
        sK[i4 + 2][s] = __expf(kv.z); sK[i4 + 3][s] = __expf(kv.w);
        float4 vv = *(const float4*)(base + 64 + i4);
        float4 ev = {__expf(vv.x), __expf(vv.y), __expf(vv.z), __expf(vv.w)};
        *(float4*)&sV[s][i4] = ev;
    }
    {
        int i = tid >> 3, j0 = (tid & 7) * 4;
        float4 st = *(const float4*)&state[((size_t)(h * 16 + qt) * 32 + i) * 32 + j0];
        *(float4*)&sSt[i][j0] = st;
        if (tid < 32) sZp[tid] = zs[(h * 16 + qt) * 32 + tid];
    }
    __syncthreads();

    int tk = tid & 15, tq = tid >> 4;
    {
        float p[4][4] = {};
        #pragma unroll
        for (int i = 0; i < 32; i++) {
            float4 a4 = *(float4*)&sQ[i][tq * 4];
            float4 b4 = *(float4*)&sK[i][tk * 4];
            float ar[4] = {a4.x, a4.y, a4.z, a4.w};
            float br[4] = {b4.x, b4.y, b4.z, b4.w};
            #pragma unroll
            for (int r = 0; r < 4; r++)
                #pragma unroll
                for (int c = 0; c < 4; c++)
                    p[r][c] += ar[r] * br[c];
        }
        #pragma unroll
        for (int r = 0; r < 4; r++)
            #pragma unroll
            for (int c = 0; c < 4; c++)
                sP[tq * 4 + r][tk * 4 + c] =
                    (tk * 4 + c > tq * 4 + r) ? 0.f : p[r][c];
    }
    __syncthreads();

    int vx = tid & 7, ry = tid >> 3;
    float Sacc[2][4] = {};
    float Zacc[2] = {};
    {
        #pragma unroll 4
        for (int i = 0; i < 32; i++) {
            float q0 = sQ[i][ry * 2 + 0];
            float q1 = sQ[i][ry * 2 + 1];
            float4 st = *(float4*)&sSt[i][vx * 4];
            Sacc[0][0] += q0 * st.x; Sacc[0][1] += q0 * st.y;
            Sacc[0][2] += q0 * st.z; Sacc[0][3] += q0 * st.w;
            Sacc[1][0] += q1 * st.x; Sacc[1][1] += q1 * st.y;
            Sacc[1][2] += q1 * st.z; Sacc[1][3] += q1 * st.w;
            if (vx == 0) {
                float z = sZp[i];
                Zacc[0] += q0 * z; Zacc[1] += q1 * z;
            }
        }
        #pragma unroll 8
        for (int s = 0; s < 64; s++) {
            float p0 = sP[ry * 2 + 0][s];
            float p1 = sP[ry * 2 + 1][s];
            float4 vv = *(float4*)&sV[s][vx * 4];
            Sacc[0][0] += p0 * vv.x; Sacc[0][1] += p0 * vv.y;
            Sacc[0][2] += p0 * vv.z; Sacc[0][3] += p0 * vv.w;
            Sacc[1][0] += p1 * vv.x; Sacc[1][1] += p1 * vv.y;
            Sacc[1][2] += p1 * vv.z; Sacc[1][3] += p1 * vv.w;
            if (vx == 0) { Zacc[0] += p0; Zacc[1] += p1; }
        }
    }
    if (vx == 0) { sZ[ry * 2] = Zacc[0]; sZ[ry * 2 + 1] = Zacc[1]; }
    __syncthreads();
    #pragma unroll
    for (int r = 0; r < 2; r++) {
        int row = t0 + ry * 2 + r;
        float lz = __logf(sZ[ry * 2 + r]);
        float4 o;
        o.x = __logf(Sacc[r][0]) - lz;
        o.y = __logf(Sacc[r][1]) - lz;
        o.z = __logf(Sacc[r][2]) - lz;
        o.w = __logf(Sacc[r][3]) - lz;
        *(float4*)&att[(size_t)row * kD + h * 32 + vx * 4] = o;
    }
}

// ================================================================ launch
extern "C" void kernel_launch(void* const* d_in, const int* in_sizes, int n_in,
                              void* d_out, int out_size) {
    const int*   tok     = (const int*)  d_in[0];
    const float* embed_w = (const float*)d_in[1];
    const float* pos_w   = (const float*)d_in[2];
    const float* pos_b   = (const float*)d_in[3];
    const float* ln1_g   = (const float*)d_in[4];
    const float* ln1_b   = (const float*)d_in[5];
    const float* qkv_w   = (const float*)d_in[6];
    const float* qkv_b   = (const float*)d_in[7];
    const float* ff_w1   = (const float*)d_in[8];
    const float* ff_b1   = (const float*)d_in[9];
    const float* ff_w2   = (const float*)d_in[10];
    const float* lnf_g   = (const float*)d_in[11];
    const float* lnf_b   = (const float*)d_in[12];
    float* out = (float*)d_out;

    float *x, *xn, *hbuf, *y, *att, *g, *st, *zsb;
    cudaGetSymbolAddress((void**)&x,    g_x);
    cudaGetSymbolAddress((void**)&xn,   g_xn);
    cudaGetSymbolAddress((void**)&hbuf, g_h);
    cudaGetSymbolAddress((void**)&y,    g_y);
    cudaGetSymbolAddress((void**)&att,  g_att);
    cudaGetSymbolAddress((void**)&g,    g_g);
    cudaGetSymbolAddress((void**)&st,   g_state);
    cudaGetSymbolAddress((void**)&zsb,  g_zs);

    // 1. embedding
    embed_kernel<<<(kS * 192 + 255) / 256, 256>>>(tok, embed_w, x);

    // 2. positional
    gemm_mma_kernel<false><<<dim3(kFF / 64, kS / 128), 256>>>(
        x, pos_w, pos_b, nullptr, hbuf, kFF);
    pos_scan_kernel<<<6, 128>>>(hbuf, x);

    // 3. layers
    for (int l = 0; l < kL; l++) {
        ln_kernel<<<kS, 256>>>(x, ln1_g + (size_t)l * kD, ln1_b + (size_t)l * kD, xn);
        gemm_mma_kernel<false><<<dim3(kQKV / 64, kS / 128), 256>>>(
            xn, qkv_w + (size_t)l * kD * kQKV, qkv_b + (size_t)l * kQKV, nullptr, y, kQKV);
        attn_state_kernel<<<dim3(16, kH), 256>>>(y, st, zsb);
        attn_prefix_kernel<<<kH, 1024>>>(st, zsb);
        attn_out_kernel<<<dim3(16, kH), 256>>>(y, st, zsb, att);
        gemm_mma_kernel<false><<<dim3(kFF / 64, kS / 128), 256>>>(
            att, ff_w1 + (size_t)l * kD * kFF, ff_b1 + (size_t)l * kFF, nullptr, hbuf, kFF);
        glu_kernel<<<(kS * 192 + 255) / 256, 256>>>(hbuf, g);
        gemm_mma_kernel<false><<<dim3(kD / 64, kS / 128), 256>>>(
            g, ff_w2 + (size_t)l * kD * kD, nullptr, x, x, kD);
    }

    // 4. final LN + logits
    ln_kernel<<<kS, 256>>>(x, lnf_g, lnf_b, xn);
    gemm_mma_kernel<true><<<dim3(kV / 64, kS / 128), 256>>>(
        xn, embed_w, nullptr, nullptr, out, kV);
}

// round 13
// speedup vs baseline: 1.9098x; 1.0018x over previous
#include <cuda_runtime.h>
#include <cuda_fp16.h>
#include <math.h>
#include <stdint.h>

// Problem constants
constexpr int kS    = 1024;
constexpr int kD    = 768;
constexpr int kL    = 12;
constexpr int kH    = 24;
constexpr int kQKV  = 2304;   // H*(32+32+32)
constexpr int kFF   = 1536;   // 2*D
constexpr int kV    = 50304;
constexpr int kK    = 768;    // shared GEMM K

// Scratch (device globals; no allocation allowed)
__device__ float g_x    [kS * kD];
__device__ float g_xn   [kS * kD];
__device__ float g_h    [kS * kFF];
__device__ float g_y    [kS * kQKV];
__device__ float g_att  [kS * kD];
__device__ float g_g    [kS * kD];
__device__ float g_state[kH * 16 * 32 * 32];
__device__ float g_zs   [kH * 16 * 32];

// ================================================================ fp16-split mma GEMM
// C[M,N] = A[M,K=768] @ op(B) (+bias) (+addsrc), fp32 in/out.
// A = Ahi + Alo (fp16 pair, in-kernel split; A-side error ~2^-24).
// B -> Bhi only (fp16 rn; the dropped residual gives ~1e-4 rel err, within budget).
// C = Ahi*Bhi + Alo*Bhi  -> 2 MMAs per (f,j) per k16 instead of 3.
// BM=128, BN=64, BK=16, 256 threads (8 warps, 4m x 2n), warp tile 32x32.
// Fragments via ldmatrix.x4; smem row r at word offset r*12 (48B stride:
// 16B-aligned rows; 3r mod 8 is a permutation -> ldmatrix conflict-free).
constexpr int kNIter = kK / 16;   // 48
constexpr int kABuf  = 1536;      // words per A plane buffer (128 rows x 12)
constexpr int kBBuf  = 768;       // words per B plane buffer (64 rows x 12)
constexpr int SAH = 0;                    // A hi: 2 bufs
constexpr int SAL = 2 * kABuf;            // A lo: 2 bufs
constexpr int SBH = 4 * kABuf;            // B hi: 2 bufs
constexpr int kSmWords = 4 * kABuf + 2 * kBBuf;   // 7680 words = 30 KB

__device__ __forceinline__ uint32_t pack_h2_split(float x, float y, float& lx, float& ly) {
    __half2 h = __floats2half2_rn(x, y);
    lx = x - __low2float(h);
    ly = y - __high2float(h);
    return *reinterpret_cast<uint32_t*>(&h);
}
__device__ __forceinline__ uint32_t pack_h2(float x, float y) {
    __half2 h = __floats2half2_rn(x, y);
    return *reinterpret_cast<uint32_t*>(&h);
}

__device__ __forceinline__ void mma_fp16(float c[4],
                                         const uint32_t a[4],
                                         const uint32_t b[2]) {
    asm volatile(
        "mma.sync.aligned.m16n8k16.row.col.f32.f16.f16.f32 "
        "{%0,%1,%2,%3}, {%4,%5,%6,%7}, {%8,%9}, {%0,%1,%2,%3};"
        : "+f"(c[0]), "+f"(c[1]), "+f"(c[2]), "+f"(c[3])
        : "r"(a[0]), "r"(a[1]), "r"(a[2]), "r"(a[3]),
          "r"(b[0]), "r"(b[1]));
}
__device__ __forceinline__ void ldsm4(uint32_t r[4], uint32_t addr) {
    asm volatile("ldmatrix.sync.aligned.m8n8.x4.shared.b16 {%0,%1,%2,%3}, [%4];"
        : "=r"(r[0]), "=r"(r[1]), "=r"(r[2]), "=r"(r[3]) : "r"(addr));
}

template <bool TRANSB>
__global__ void __launch_bounds__(256, 2)
gemm_mma_kernel(const float* __restrict__ A, const float* __restrict__ B,
                const float* __restrict__ bias, const float* __restrict__ addsrc,
                float* __restrict__ C, int N) {
    __shared__ uint32_t sm[kSmWords];

    int tid  = threadIdx.x;
    int lane = tid & 31;
    int w    = tid >> 5;
    int g    = lane >> 2;
    int t4   = lane & 3;
    int n0   = blockIdx.x * 64;
    int m0   = blockIdx.y * 128;
    int wm   = (w & 3) * 32;
    int wn   = (w >> 2) * 32;

    // ldmatrix lane addresses (loop-invariant word offsets)
    int l8 = lane & 7, quad = lane >> 3;
    int rowA0 = wm + (quad & 1) * 8 + l8;
    int offA0 = rowA0 * 12 + (quad >> 1) * 4;
    int offA1 = (rowA0 + 16) * 12 + (quad >> 1) * 4;
    int rowB0 = wn + (quad >> 1) * 8 + l8;
    int offB0 = rowB0 * 12 + (quad & 1) * 4;
    int offB2 = (rowB0 + 16) * 12 + (quad & 1) * 4;

    uint32_t su = (uint32_t)__cvta_generic_to_shared(sm);
    uint32_t aHi0 = su + (SAH + offA0) * 4, aHi1 = su + (SAH + offA1) * 4;
    uint32_t aLo0 = su + (SAL + offA0) * 4, aLo1 = su + (SAL + offA1) * 4;
    uint32_t bHi0 = su + (SBH + offB0) * 4, bHi2 = su + (SBH + offB2) * 4;

    // ---------- staging maps (identical structure to the proven r9 kernel)
    int srow = tid >> 2;          // 0..63
    int scol = (tid & 3) * 4;     // 0,4,8,12
    const float* gA0 = A + (size_t)(m0 + srow) * kK + scol;
    const float* gA1 = A + (size_t)(m0 + srow + 64) * kK + scol;
    int wA0 = srow * 12 + (tid & 3) * 2;
    int wA1 = (srow + 64) * 12 + (tid & 3) * 2;

    const float* gBt = nullptr;
    const float* gBc = nullptr;
    int wB = 0;
    if (TRANSB) {
        gBt = B + (size_t)(n0 + srow) * kK + scol;
        wB  = srow * 12 + (tid & 3) * 2;
    } else {
        int q = tid >> 6, nn = tid & 63;
        gBc = B + (size_t)(q * 4) * N + n0 + nn;
        wB  = nn * 12 + 2 * q;
    }

    float acc[2][4][4];
    #pragma unroll
    for (int f = 0; f < 2; f++)
        #pragma unroll
        for (int j = 0; j < 4; j++)
            #pragma unroll
            for (int u = 0; u < 4; u++) acc[f][j][u] = 0.f;

    float4 ra0, ra1, rb4;
    float rbn[4];

    auto ldg = [&](int it) {
        int k0 = it * 16;
        ra0 = *(const float4*)(gA0 + k0);
        ra1 = *(const float4*)(gA1 + k0);
        if (TRANSB) {
            rb4 = *(const float4*)(gBt + k0);
        } else {
            const float* p = gBc + (size_t)k0 * N;
            #pragma unroll
            for (int u = 0; u < 4; u++) rbn[u] = p[(size_t)u * N];
        }
    };

    auto sts = [&](int buf) {
        int boA = buf * kABuf, boB = buf * kBBuf;
        float l0, l1, l2, l3;
        uint32_t h0 = pack_h2_split(ra0.x, ra0.y, l0, l1);
        uint32_t h1 = pack_h2_split(ra0.z, ra0.w, l2, l3);
        sm[SAH + boA + wA0] = h0; sm[SAH + boA + wA0 + 1] = h1;
        sm[SAL + boA + wA0] = pack_h2(l0, l1);
        sm[SAL + boA + wA0 + 1] = pack_h2(l2, l3);
        h0 = pack_h2_split(ra1.x, ra1.y, l0, l1);
        h1 = pack_h2_split(ra1.z, ra1.w, l2, l3);
        sm[SAH + boA + wA1] = h0; sm[SAH + boA + wA1 + 1] = h1;
        sm[SAL + boA + wA1] = pack_h2(l0, l1);
        sm[SAL + boA + wA1 + 1] = pack_h2(l2, l3);
        if (TRANSB) {
            sm[SBH + boB + wB]     = pack_h2(rb4.x, rb4.y);
            sm[SBH + boB + wB + 1] = pack_h2(rb4.z, rb4.w);
        } else {
            sm[SBH + boB + wB]     = pack_h2(rbn[0], rbn[1]);
            sm[SBH + boB + wB + 1] = pack_h2(rbn[2], rbn[3]);
        }
    };

    ldg(0);
    sts(0);
    __syncthreads();

    for (int it = 0; it < kNIter; it++) {
        int buf = it & 1;
        uint32_t oA = (uint32_t)(buf * kABuf * 4);
        uint32_t oB = (uint32_t)(buf * kBBuf * 4);
        if (it + 1 < kNIter) ldg(it + 1);

        uint32_t ah[2][4], al[2][4], bq0[4], bq2[4];
        ldsm4(ah[0], aHi0 + oA);
        ldsm4(ah[1], aHi1 + oA);
        ldsm4(al[0], aLo0 + oA);
        ldsm4(al[1], aLo1 + oA);
        ldsm4(bq0, bHi0 + oB);
        ldsm4(bq2, bHi2 + oB);

        uint32_t bh[4][2] = {{bq0[0], bq0[1]}, {bq0[2], bq0[3]},
                             {bq2[0], bq2[1]}, {bq2[2], bq2[3]}};

        #pragma unroll
        for (int f = 0; f < 2; f++)
            #pragma unroll
            for (int j = 0; j < 4; j++) {
                mma_fp16(acc[f][j], ah[f], bh[j]);
                mma_fp16(acc[f][j], al[f], bh[j]);
            }

        if (it + 1 < kNIter) sts(buf ^ 1);
        __syncthreads();
    }

    // epilogue
    #pragma unroll
    for (int f = 0; f < 2; f++) {
        int r0 = m0 + wm + f * 16 + g;
        #pragma unroll
        for (int j = 0; j < 4; j++) {
            int n = n0 + wn + j * 8 + t4 * 2;
            float2 lo = {acc[f][j][0], acc[f][j][1]};
            float2 hi = {acc[f][j][2], acc[f][j][3]};
            if (bias) {
                float2 b2 = *(const float2*)(bias + n);
                lo.x += b2.x; lo.y += b2.y;
                hi.x += b2.x; hi.y += b2.y;
            }
            size_t o0 = (size_t)r0 * N + n;
            size_t o1 = (size_t)(r0 + 8) * N + n;
            if (addsrc) {
                float2 s0 = *(const float2*)(addsrc + o0);
                float2 s1 = *(const float2*)(addsrc + o1);
                lo.x += s0.x; lo.y += s0.y;
                hi.x += s1.x; hi.y += s1.y;
            }
            *(float2*)(C + o0) = lo;
            *(float2*)(C + o1) = hi;
        }
    }
}

// ================================================================ embed gather (float4)
__global__ void embed_kernel(const int* __restrict__ tok,
                             const float* __restrict__ ew,
                             float* __restrict__ x) {
    int idx = blockIdx.x * blockDim.x + threadIdx.x;
    if (idx < kS * (kD / 4)) {
        int t = idx / 192, d4 = idx - t * 192;
        float4 v = *(const float4*)(ew + (size_t)tok[t] * kD + d4 * 4);
        *(float4*)(x + (size_t)t * kD + d4 * 4) = v;
    }
}

// ================================================================ layernorm
__global__ void ln_kernel(const float* __restrict__ x,
                          const float* __restrict__ gw,
                          const float* __restrict__ bw,
                          float* __restrict__ out) {
    int row = blockIdx.x;
    int tid = threadIdx.x;  // 256
    const float* xr = x + (size_t)row * kD;
    float v0 = xr[tid], v1 = xr[tid + 256], v2 = xr[tid + 512];
    float s = v0 + v1 + v2;
    __shared__ float red[8];
    unsigned lane = tid & 31, wid = tid >> 5;
    #pragma unroll
    for (int o = 16; o > 0; o >>= 1) s += __shfl_down_sync(0xffffffffu, s, o);
    if (lane == 0) red[wid] = s;
    __syncthreads();
    float tot = 0.f;
    #pragma unroll
    for (int i = 0; i < 8; i++) tot += red[i];
    float m = tot * (1.f / 768.f);
    float d0 = v0 - m, d1 = v1 - m, d2 = v2 - m;
    float s2 = d0 * d0 + d1 * d1 + d2 * d2;
    __syncthreads();
    #pragma unroll
    for (int o = 16; o > 0; o >>= 1) s2 += __shfl_down_sync(0xffffffffu, s2, o);
    if (lane == 0) red[wid] = s2;
    __syncthreads();
    float tot2 = 0.f;
    #pragma unroll
    for (int i = 0; i < 8; i++) tot2 += red[i];
    float scale = rsqrtf(tot2 * (1.f / 768.f) + 1e-5f);
    float* orow = out + (size_t)row * kD;
    orow[tid]       = d0 * scale * gw[tid]       + bw[tid];
    orow[tid + 256] = d1 * scale * gw[tid + 256] + bw[tid + 256];
    orow[tid + 512] = d2 * scale * gw[tid + 512] + bw[tid + 512];
}

// ================================================================ pos scan
__global__ void pos_scan_kernel(const float* __restrict__ h, float* __restrict__ x) {
    int d = blockIdx.x * blockDim.x + threadIdx.x;
    if (d >= kD) return;
    float a = 0.f, Lv = 0.f;
    for (int t = 0; t < kS; t++) {
        float hc = h[(size_t)t * kFF + d];
        float hl = h[(size_t)t * kFF + kD + d];
        float lc = fminf(hc, 0.f) - log1pf(__expf(-fabsf(hc)));
        a += lc;
        float v = hl - a;
        float mx = fmaxf(Lv, v), mn = fminf(Lv, v);
        Lv = mx + log1pf(__expf(mn - mx));
        x[(size_t)t * kD + d] += a + Lv;
    }
}

// ================================================================ GLU (float4)
__global__ void glu_kernel(const float* __restrict__ z, float* __restrict__ g) {
    int idx = blockIdx.x * blockDim.x + threadIdx.x;
    if (idx < kS * (kD / 4)) {
        int t = idx / 192, d4 = idx - t * 192;
        float4 a = *(const float4*)(z + (size_t)t * kFF + d4 * 4);
        float4 b = *(const float4*)(z + (size_t)t * kFF + kD + d4 * 4);
        float4 o;
        o.x = a.x / (1.f + __expf(-b.x));
        o.y = a.y / (1.f + __expf(-b.y));
        o.z = a.z / (1.f + __expf(-b.z));
        o.w = a.w / (1.f + __expf(-b.w));
        *(float4*)(g + (size_t)t * kD + d4 * 4) = o;
    }
}

// ================================================================ chunked attention
__global__ void __launch_bounds__(256)
attn_state_kernel(const float* __restrict__ y, float* __restrict__ state,
                  float* __restrict__ zs) {
    __shared__ float sK[64][36];
    __shared__ float sV[64][36];
    int t = blockIdx.x, h = blockIdx.y;
    int tid = threadIdx.x;
    int i4 = (tid & 7) * 4, rr = tid >> 3;
    #pragma unroll
    for (int rep = 0; rep < 2; rep++) {
        int s = rr + rep * 32;
        const float* base = y + (size_t)(t * 64 + s) * kQKV + h * 96;
        float4 kv = *(const float4*)(base + 32 + i4);
        float4 vv = *(const float4*)(base + 64 + i4);
        float4 ek = {__expf(kv.x), __expf(kv.y), __expf(kv.z), __expf(kv.w)};
        float4 ev = {__expf(vv.x), __expf(vv.y), __expf(vv.z), __expf(vv.w)};
        *(float4*)&sK[s][i4] = ek;
        *(float4*)&sV[s][i4] = ev;
    }
    __syncthreads();
    int i = tid >> 3, j0 = (tid & 7) * 4;
    float a0 = 0.f, a1 = 0.f, a2 = 0.f, a3 = 0.f;
    #pragma unroll 4
    for (int s = 0; s < 64; s++) {
        float k = sK[s][i];
        float4 v = *(float4*)&sV[s][j0];
        a0 += k * v.x; a1 += k * v.y; a2 += k * v.z; a3 += k * v.w;
    }
    float4 o = {a0, a1, a2, a3};
    *(float4*)&state[((size_t)(h * 16 + t) * 32 + i) * 32 + j0] = o;
    if (tid < 32) {
        float z = 0.f;
        #pragma unroll 4
        for (int s = 0; s < 64; s++) z += sK[s][tid];
        zs[(h * 16 + t) * 32 + tid] = z;
    }
}

// prefix over 16 tiles (prefetch then scan)
__global__ void __launch_bounds__(1024)
attn_prefix_kernel(float* __restrict__ state, float* __restrict__ zs) {
    int h = blockIdx.x;
    int idx = threadIdx.x;
    float v[16];
    #pragma unroll
    for (int t = 0; t < 16; t++)
        v[t] = state[(size_t)(h * 16 + t) * 1024 + idx];
    float run = 0.f;
    #pragma unroll
    for (int t = 0; t < 16; t++) {
        state[(size_t)(h * 16 + t) * 1024 + idx] = run;
        run += v[t];
    }
    if (idx < 32) {
        float zv[16];
        #pragma unroll
        for (int t = 0; t < 16; t++) zv[t] = zs[(h * 16 + t) * 32 + idx];
        float rz = 0.f;
        #pragma unroll
        for (int t = 0; t < 16; t++) {
            zs[(h * 16 + t) * 32 + idx] = rz;
            rz += zv[t];
        }
    }
}

__global__ void __launch_bounds__(256)
attn_out_kernel(const float* __restrict__ y, const float* __restrict__ state,
                const float* __restrict__ zs, float* __restrict__ att) {
    __shared__ float sQ[32][64];
    __shared__ float sK[32][64];
    __shared__ float sV[64][36];
    __shared__ float sSt[32][36];
    __shared__ float sZp[32];
    __shared__ float sP[64][65];
    __shared__ float sZ[64];

    int qt = blockIdx.x, h = blockIdx.y;
    int t0 = qt * 64;
    int tid = threadIdx.x;
    int i4 = (tid & 7) * 4, rr = tid >> 3;

    #pragma unroll
    for (int rep = 0; rep < 2; rep++) {
        int s = rr + rep * 32;
        const float* base = y + (size_t)(t0 + s) * kQKV + h * 96;
        float4 qv = *(const float4*)(base + i4);
        sQ[i4 + 0][s] = __expf(qv.x); sQ[i4 + 1][s] = __expf(qv.y);
        sQ[i4 + 2][s] = __expf(qv.z); sQ[i4 + 3][s] = __expf(qv.w);
        float4 kv = *(const float4*)(base + 32 + i4);
        sK[i4 + 0][s] = __expf(kv.x); sK[i4 + 1][s] = __expf(kv.y);
        sK[i4 + 2][s] = __expf(kv.z); sK[i4 + 3][s] = __expf(kv.w);
        float4 vv = *(const float4*)(base + 64 + i4);
        float4 ev = {__expf(vv.x), __expf(vv.y), __expf(vv.z), __expf(vv.w)};
        *(float4*)&sV[s][i4] = ev;
    }
    {
        int i = tid >> 3, j0 = (tid & 7) * 4;
        float4 st = *(const float4*)&state[((size_t)(h * 16 + qt) * 32 + i) * 32 + j0];
        *(float4*)&sSt[i][j0] = st;
        if (tid < 32) sZp[tid] = zs[(h * 16 + qt) * 32 + tid];
    }
    __syncthreads();

    int tk = tid & 15, tq = tid >> 4;
    {
        float p[4][4] = {};
        #pragma unroll
        for (int i = 0; i < 32; i++) {
            float4 a4 = *(float4*)&sQ[i][tq * 4];
            float4 b4 = *(float4*)&sK[i][tk * 4];
            float ar[4] = {a4.x, a4.y, a4.z, a4.w};
            float br[4] = {b4.x, b4.y, b4.z, b4.w};
            #pragma unroll
            for (int r = 0; r < 4; r++)
                #pragma unroll
                for (int c = 0; c < 4; c++)
                    p[r][c] += ar[r] * br[c];
        }
        #pragma unroll
        for (int r = 0; r < 4; r++)
            #pragma unroll
            for (int c = 0; c < 4; c++)
                sP[tq * 4 + r][tk * 4 + c] =
                    (tk * 4 + c > tq * 4 + r) ? 0.f : p[r][c];
    }
    __syncthreads();

    int vx = tid & 7, ry = tid >> 3;
    float Sacc[2][4] = {};
    float Zacc[2] = {};
    {
        #pragma unroll 4
        for (int i = 0; i < 32; i++) {
            float q0 = sQ[i][ry * 2 + 0];
            float q1 = sQ[i][ry * 2 + 1];
            float4 st = *(float4*)&sSt[i][vx * 4];
            Sacc[0][0] += q0 * st.x; Sacc[0][1] += q0 * st.y;
            Sacc[0][2] += q0 * st.z; Sacc[0][3] += q0 * st.w;
            Sacc[1][0] += q1 * st.x; Sacc[1][1] += q1 * st.y;
            Sacc[1][2] += q1 * st.z; Sacc[1][3] += q1 * st.w;
            if (vx == 0) {
                float z = sZp[i];
                Zacc[0] += q0 * z; Zacc[1] += q1 * z;
            }
        }
        #pragma unroll 8
        for (int s = 0; s < 64; s++) {
            float p0 = sP[ry * 2 + 0][s];
            float p1 = sP[ry * 2 + 1][s];
            float4 vv = *(float4*)&sV[s][vx * 4];
            Sacc[0][0] += p0 * vv.x; Sacc[0][1] += p0 * vv.y;
            Sacc[0][2] += p0 * vv.z; Sacc[0][3] += p0 * vv.w;
            Sacc[1][0] += p1 * vv.x; Sacc[1][1] += p1 * vv.y;
            Sacc[1][2] += p1 * vv.z; Sacc[1][3] += p1 * vv.w;
            if (vx == 0) { Zacc[0] += p0; Zacc[1] += p1; }
        }
    }
    if (vx == 0) { sZ[ry * 2] = Zacc[0]; sZ[ry * 2 + 1] = Zacc[1]; }
    __syncthreads();
    #pragma unroll
    for (int r = 0; r < 2; r++) {
        int row = t0 + ry * 2 + r;
        float lz = __logf(sZ[ry * 2 + r]);
        float4 o;
        o.x = __logf(Sacc[r][0]) - lz;
        o.y = __logf(Sacc[r][1]) - lz;
        o.z = __logf(Sacc[r][2]) - lz;
        o.w = __logf(Sacc[r][3]) - lz;
        *(float4*)&att[(size_t)row * kD + h * 32 + vx * 4] = o;
    }
}

// ================================================================ launch
extern "C" void kernel_launch(void* const* d_in, const int* in_sizes, int n_in,
                              void* d_out, int out_size) {
    const int*   tok     = (const int*)  d_in[0];
    const float* embed_w = (const float*)d_in[1];
    const float* pos_w   = (const float*)d_in[2];
    const float* pos_b   = (const float*)d_in[3];
    const float* ln1_g   = (const float*)d_in[4];
    const float* ln1_b   = (const float*)d_in[5];
    const float* qkv_w   = (const float*)d_in[6];
    const float* qkv_b   = (const float*)d_in[7];
    const float* ff_w1   = (const float*)d_in[8];
    const float* ff_b1   = (const float*)d_in[9];
    const float* ff_w2   = (const float*)d_in[10];
    const float* lnf_g   = (const float*)d_in[11];
    const float* lnf_b   = (const float*)d_in[12];
    float* out = (float*)d_out;

    float *x, *xn, *hbuf, *y, *att, *g, *st, *zsb;
    cudaGetSymbolAddress((void**)&x,    g_x);
    cudaGetSymbolAddress((void**)&xn,   g_xn);
    cudaGetSymbolAddress((void**)&hbuf, g_h);
    cudaGetSymbolAddress((void**)&y,    g_y);
    cudaGetSymbolAddress((void**)&att,  g_att);
    cudaGetSymbolAddress((void**)&g,    g_g);
    cudaGetSymbolAddress((void**)&st,   g_state);
    cudaGetSymbolAddress((void**)&zsb,  g_zs);

    // 1. embedding
    embed_kernel<<<(kS * 192 + 255) / 256, 256>>>(tok, embed_w, x);

    // 2. positional
    gemm_mma_kernel<false><<<dim3(kFF / 64, kS / 128), 256>>>(
        x, pos_w, pos_b, nullptr, hbuf, kFF);
    pos_scan_kernel<<<6, 128>>>(hbuf, x);

    // 3. layers
    for (int l = 0; l < kL; l++) {
        ln_kernel<<<kS, 256>>>(x, ln1_g + (size_t)l * kD, ln1_b + (size_t)l * kD, xn);
        gemm_mma_kernel<false><<<dim3(kQKV / 64, kS / 128), 256>>>(
            xn, qkv_w + (size_t)l * kD * kQKV, qkv_b + (size_t)l * kQKV, nullptr, y, kQKV);
        attn_state_kernel<<<dim3(16, kH), 256>>>(y, st, zsb);
        attn_prefix_kernel<<<kH, 1024>>>(st, zsb);
        attn_out_kernel<<<dim3(16, kH), 256>>>(y, st, zsb, att);
        gemm_mma_kernel<false><<<dim3(kFF / 64, kS / 128), 256>>>(
            att, ff_w1 + (size_t)l * kD * kFF, ff_b1 + (size_t)l * kFF, nullptr, hbuf, kFF);
        glu_kernel<<<(kS * 192 + 255) / 256, 256>>>(hbuf, g);
        gemm_mma_kernel<false><<<dim3(kD / 64, kS / 128), 256>>>(
            g, ff_w2 + (size_t)l * kD * kD, nullptr, x, x, kD);
    }

    // 4. final LN + logits
    ln_kernel<<<kS, 256>>>(x, lnf_g, lnf_b, xn);
    gemm_mma_kernel<true><<<dim3(kV / 64, kS / 128), 256>>>(
        xn, embed_w, nullptr, nullptr, out, kV);
}

// round 14
// speedup vs baseline: 2.1626x; 1.1324x over previous
#include <cuda_runtime.h>
#include <cuda_fp16.h>
#include <math.h>
#include <stdint.h>

// Problem constants
constexpr int kS    = 1024;
constexpr int kD    = 768;
constexpr int kL    = 12;
constexpr int kH    = 24;
constexpr int kQKV  = 2304;   // H*(32+32+32)
constexpr int kFF   = 1536;   // 2*D
constexpr int kV    = 50304;
constexpr int kK    = 768;    // shared GEMM K

// Scratch (device globals; no allocation allowed)
__device__ float g_x    [kS * kD];
__device__ float g_xn   [kS * kD];
__device__ float g_h    [kS * kFF];
__device__ float g_y    [kS * kQKV];
__device__ float g_att  [kS * kD];
__device__ float g_g    [kS * kD];
__device__ float g_state[kH * 16 * 32 * 32];
__device__ float g_zs   [kH * 16 * 32];

// ================================================================ fp16-split mma GEMM
// C[M,N] = A[M,K=768] @ op(B) (+bias) (+addsrc), fp32 in/out.
// A = Ahi + Alo (fp16 pair, split in staging); B -> fp16 rn (hi only).
// C = Ahi*Bhi + Alo*Bhi.
// BM=128, BN=64, BK=32, 256 threads (8 warps, 4m x 2n), warp tile 32x32.
// smem row r at word offset r*20 (80B stride: rows 16B-aligned; 16B-slot
// = 5r mod 8 is a permutation -> ldmatrix conflict-free).
constexpr int kNIter = kK / 32;   // 24
constexpr int kSW    = 20;        // words per smem row
constexpr int kABuf  = 128 * kSW; // 2560 words per A plane buffer
constexpr int kBBuf  = 64 * kSW;  // 1280 words per B plane buffer
constexpr int SAH = 0;                    // A hi: 2 bufs
constexpr int SAL = 2 * kABuf;            // A lo: 2 bufs
constexpr int SBH = 4 * kABuf;            // B hi: 2 bufs
constexpr int kSmBytes = (4 * kABuf + 2 * kBBuf) * 4;   // 51200

__device__ __forceinline__ uint32_t pack_h2_split(float x, float y, float& lx, float& ly) {
    __half2 h = __floats2half2_rn(x, y);
    lx = x - __low2float(h);
    ly = y - __high2float(h);
    return *reinterpret_cast<uint32_t*>(&h);
}
__device__ __forceinline__ uint32_t pack_h2(float x, float y) {
    __half2 h = __floats2half2_rn(x, y);
    return *reinterpret_cast<uint32_t*>(&h);
}

__device__ __forceinline__ void mma_fp16(float c[4],
                                         const uint32_t a[4],
                                         const uint32_t b[2]) {
    asm volatile(
        "mma.sync.aligned.m16n8k16.row.col.f32.f16.f16.f32 "
        "{%0,%1,%2,%3}, {%4,%5,%6,%7}, {%8,%9}, {%0,%1,%2,%3};"
        : "+f"(c[0]), "+f"(c[1]), "+f"(c[2]), "+f"(c[3])
        : "r"(a[0]), "r"(a[1]), "r"(a[2]), "r"(a[3]),
          "r"(b[0]), "r"(b[1]));
}
__device__ __forceinline__ void ldsm4(uint32_t r[4], uint32_t addr) {
    asm volatile("ldmatrix.sync.aligned.m8n8.x4.shared.b16 {%0,%1,%2,%3}, [%4];"
        : "=r"(r[0]), "=r"(r[1]), "=r"(r[2]), "=r"(r[3]) : "r"(addr));
}

template <bool TRANSB>
__global__ void __launch_bounds__(256, 2)
gemm_mma_kernel(const float* __restrict__ A, const float* __restrict__ B,
                const float* __restrict__ bias, const float* __restrict__ addsrc,
                float* __restrict__ C, int N) {
    extern __shared__ uint32_t sm[];

    int tid  = threadIdx.x;
    int lane = tid & 31;
    int w    = tid >> 5;
    int g    = lane >> 2;
    int t4   = lane & 3;
    int n0   = blockIdx.x * 64;
    int m0   = blockIdx.y * 128;
    int wm   = (w & 3) * 32;
    int wn   = (w >> 2) * 32;

    // ldmatrix lane addresses (word offsets; per-k16-half add 8 words = 32B)
    int l8 = lane & 7, quad = lane >> 3;
    int rowA0 = wm + (quad & 1) * 8 + l8;
    int offA0 = rowA0 * kSW + (quad >> 1) * 4;
    int offA1 = (rowA0 + 16) * kSW + (quad >> 1) * 4;
    int rowB0 = wn + (quad >> 1) * 8 + l8;
    int offB0 = rowB0 * kSW + (quad & 1) * 4;
    int offB2 = (rowB0 + 16) * kSW + (quad & 1) * 4;

    uint32_t su = (uint32_t)__cvta_generic_to_shared(sm);
    uint32_t aHi0 = su + (SAH + offA0) * 4, aHi1 = su + (SAH + offA1) * 4;
    uint32_t aLo0 = su + (SAL + offA0) * 4, aLo1 = su + (SAL + offA1) * 4;
    uint32_t bHi0 = su + (SBH + offB0) * 4, bHi2 = su + (SBH + offB2) * 4;

    // ---------- staging maps
    int srow = tid >> 2;          // 0..63
    int c4   = tid & 3;
    int scol = c4 * 8;            // 8 consecutive k floats
    const float* gA0 = A + (size_t)(m0 + srow) * kK + scol;
    const float* gA1 = A + (size_t)(m0 + srow + 64) * kK + scol;
    int wA0 = srow * kSW + c4 * 4;
    int wA1 = (srow + 64) * kSW + c4 * 4;

    const float* gBt = nullptr;
    const float* gBc = nullptr;
    int wB = 0;
    if (TRANSB) {   // 64 n-rows x 32 k-floats; 4 threads per row, 8 k each
        gBt = B + (size_t)(n0 + srow) * kK + scol;
        wB  = srow * kSW + c4 * 4;
    } else {        // 32 k-rows x 64 n-cols; thread (q,nn): rows q*8..q*8+7
        int q = tid >> 6, nn = tid & 63;
        gBc = B + (size_t)(q * 8) * N + n0 + nn;
        wB  = nn * kSW + q * 4;
    }

    float acc[2][4][4];
    #pragma unroll
    for (int f = 0; f < 2; f++)
        #pragma unroll
        for (int j = 0; j < 4; j++)
            #pragma unroll
            for (int u = 0; u < 4; u++) acc[f][j][u] = 0.f;

    float4 ra0a, ra0b, ra1a, ra1b, rbta, rbtb;
    float rbn[8];

    auto ldg = [&](int it) {
        int k0 = it * 32;
        ra0a = *(const float4*)(gA0 + k0);
        ra0b = *(const float4*)(gA0 + k0 + 4);
        ra1a = *(const float4*)(gA1 + k0);
        ra1b = *(const float4*)(gA1 + k0 + 4);
        if (TRANSB) {
            rbta = *(const float4*)(gBt + k0);
            rbtb = *(const float4*)(gBt + k0 + 4);
        } else {
            const float* p = gBc + (size_t)k0 * N;
            #pragma unroll
            for (int u = 0; u < 8; u++) rbn[u] = p[(size_t)u * N];
        }
    };

    auto sts = [&](int buf) {
        int boA = buf * kABuf, boB = buf * kBBuf;
        float l0, l1, l2, l3, l4, l5, l6, l7;
        // A row group 0
        uint32_t h0 = pack_h2_split(ra0a.x, ra0a.y, l0, l1);
        uint32_t h1 = pack_h2_split(ra0a.z, ra0a.w, l2, l3);
        uint32_t h2 = pack_h2_split(ra0b.x, ra0b.y, l4, l5);
        uint32_t h3 = pack_h2_split(ra0b.z, ra0b.w, l6, l7);
        sm[SAH + boA + wA0]     = h0; sm[SAH + boA + wA0 + 1] = h1;
        sm[SAH + boA + wA0 + 2] = h2; sm[SAH + boA + wA0 + 3] = h3;
        sm[SAL + boA + wA0]     = pack_h2(l0, l1);
        sm[SAL + boA + wA0 + 1] = pack_h2(l2, l3);
        sm[SAL + boA + wA0 + 2] = pack_h2(l4, l5);
        sm[SAL + boA + wA0 + 3] = pack_h2(l6, l7);
        // A row group 1
        h0 = pack_h2_split(ra1a.x, ra1a.y, l0, l1);
        h1 = pack_h2_split(ra1a.z, ra1a.w, l2, l3);
        h2 = pack_h2_split(ra1b.x, ra1b.y, l4, l5);
        h3 = pack_h2_split(ra1b.z, ra1b.w, l6, l7);
        sm[SAH + boA + wA1]     = h0; sm[SAH + boA + wA1 + 1] = h1;
        sm[SAH + boA + wA1 + 2] = h2; sm[SAH + boA + wA1 + 3] = h3;
        sm[SAL + boA + wA1]     = pack_h2(l0, l1);
        sm[SAL + boA + wA1 + 1] = pack_h2(l2, l3);
        sm[SAL + boA + wA1 + 2] = pack_h2(l4, l5);
        sm[SAL + boA + wA1 + 3] = pack_h2(l6, l7);
        // B
        if (TRANSB) {
            sm[SBH + boB + wB]     = pack_h2(rbta.x, rbta.y);
            sm[SBH + boB + wB + 1] = pack_h2(rbta.z, rbta.w);
            sm[SBH + boB + wB + 2] = pack_h2(rbtb.x, rbtb.y);
            sm[SBH + boB + wB + 3] = pack_h2(rbtb.z, rbtb.w);
        } else {
            sm[SBH + boB + wB]     = pack_h2(rbn[0], rbn[1]);
            sm[SBH + boB + wB + 1] = pack_h2(rbn[2], rbn[3]);
            sm[SBH + boB + wB + 2] = pack_h2(rbn[4], rbn[5]);
            sm[SBH + boB + wB + 3] = pack_h2(rbn[6], rbn[7]);
        }
    };

    ldg(0);
    sts(0);
    __syncthreads();

    for (int it = 0; it < kNIter; it++) {
        int buf = it & 1;
        uint32_t oA = (uint32_t)(buf * kABuf * 4);
        uint32_t oB = (uint32_t)(buf * kBBuf * 4);
        if (it + 1 < kNIter) ldg(it + 1);

        #pragma unroll
        for (int hh = 0; hh < 2; hh++) {
            uint32_t kk = hh * 32u;   // 8 words per k16 half
            uint32_t ah[2][4], al[2][4], bq0[4], bq2[4];
            ldsm4(ah[0], aHi0 + oA + kk);
            ldsm4(ah[1], aHi1 + oA + kk);
            ldsm4(al[0], aLo0 + oA + kk);
            ldsm4(al[1], aLo1 + oA + kk);
            ldsm4(bq0, bHi0 + oB + kk);
            ldsm4(bq2, bHi2 + oB + kk);

            uint32_t bh[4][2] = {{bq0[0], bq0[1]}, {bq0[2], bq0[3]},
                                 {bq2[0], bq2[1]}, {bq2[2], bq2[3]}};

            #pragma unroll
            for (int f = 0; f < 2; f++)
                #pragma unroll
                for (int j = 0; j < 4; j++) {
                    mma_fp16(acc[f][j], ah[f], bh[j]);
                    mma_fp16(acc[f][j], al[f], bh[j]);
                }
        }

        if (it + 1 < kNIter) sts(buf ^ 1);
        __syncthreads();
    }

    // epilogue
    #pragma unroll
    for (int f = 0; f < 2; f++) {
        int r0 = m0 + wm + f * 16 + g;
        #pragma unroll
        for (int j = 0; j < 4; j++) {
            int n = n0 + wn + j * 8 + t4 * 2;
            float2 lo = {acc[f][j][0], acc[f][j][1]};
            float2 hi = {acc[f][j][2], acc[f][j][3]};
            if (bias) {
                float2 b2 = *(const float2*)(bias + n);
                lo.x += b2.x; lo.y += b2.y;
                hi.x += b2.x; hi.y += b2.y;
            }
            size_t o0 = (size_t)r0 * N + n;
            size_t o1 = (size_t)(r0 + 8) * N + n;
            if (addsrc) {
                float2 s0 = *(const float2*)(addsrc + o0);
                float2 s1 = *(const float2*)(addsrc + o1);
                lo.x += s0.x; lo.y += s0.y;
                hi.x += s1.x; hi.y += s1.y;
            }
            *(float2*)(C + o0) = lo;
            *(float2*)(C + o1) = hi;
        }
    }
}

// ================================================================ embed gather (float4)
__global__ void embed_kernel(const int* __restrict__ tok,
                             const float* __restrict__ ew,
                             float* __restrict__ x) {
    int idx = blockIdx.x * blockDim.x + threadIdx.x;
    if (idx < kS * (kD / 4)) {
        int t = idx / 192, d4 = idx - t * 192;
        float4 v = *(const float4*)(ew + (size_t)tok[t] * kD + d4 * 4);
        *(float4*)(x + (size_t)t * kD + d4 * 4) = v;
    }
}

// ================================================================ layernorm
__global__ void ln_kernel(const float* __restrict__ x,
                          const float* __restrict__ gw,
                          const float* __restrict__ bw,
                          float* __restrict__ out) {
    int row = blockIdx.x;
    int tid = threadIdx.x;  // 256
    const float* xr = x + (size_t)row * kD;
    float v0 = xr[tid], v1 = xr[tid + 256], v2 = xr[tid + 512];
    float s = v0 + v1 + v2;
    __shared__ float red[8];
    unsigned lane = tid & 31, wid = tid >> 5;
    #pragma unroll
    for (int o = 16; o > 0; o >>= 1) s += __shfl_down_sync(0xffffffffu, s, o);
    if (lane == 0) red[wid] = s;
    __syncthreads();
    float tot = 0.f;
    #pragma unroll
    for (int i = 0; i < 8; i++) tot += red[i];
    float m = tot * (1.f / 768.f);
    float d0 = v0 - m, d1 = v1 - m, d2 = v2 - m;
    float s2 = d0 * d0 + d1 * d1 + d2 * d2;
    __syncthreads();
    #pragma unroll
    for (int o = 16; o > 0; o >>= 1) s2 += __shfl_down_sync(0xffffffffu, s2, o);
    if (lane == 0) red[wid] = s2;
    __syncthreads();
    float tot2 = 0.f;
    #pragma unroll
    for (int i = 0; i < 8; i++) tot2 += red[i];
    float scale = rsqrtf(tot2 * (1.f / 768.f) + 1e-5f);
    float* orow = out + (size_t)row * kD;
    orow[tid]       = d0 * scale * gw[tid]       + bw[tid];
    orow[tid + 256] = d1 * scale * gw[tid + 256] + bw[tid + 256];
    orow[tid + 512] = d2 * scale * gw[tid + 512] + bw[tid + 512];
}

// ================================================================ pos scan
__global__ void pos_scan_kernel(const float* __restrict__ h, float* __restrict__ x) {
    int d = blockIdx.x * blockDim.x + threadIdx.x;
    if (d >= kD) return;
    float a = 0.f, Lv = 0.f;
    for (int t = 0; t < kS; t++) {
        float hc = h[(size_t)t * kFF + d];
        float hl = h[(size_t)t * kFF + kD + d];
        float lc = fminf(hc, 0.f) - log1pf(__expf(-fabsf(hc)));
        a += lc;
        float v = hl - a;
        float mx = fmaxf(Lv, v), mn = fminf(Lv, v);
        Lv = mx + log1pf(__expf(mn - mx));
        x[(size_t)t * kD + d] += a + Lv;
    }
}

// ================================================================ GLU (float4)
__global__ void glu_kernel(const float* __restrict__ z, float* __restrict__ g) {
    int idx = blockIdx.x * blockDim.x + threadIdx.x;
    if (idx < kS * (kD / 4)) {
        int t = idx / 192, d4 = idx - t * 192;
        float4 a = *(const float4*)(z + (size_t)t * kFF + d4 * 4);
        float4 b = *(const float4*)(z + (size_t)t * kFF + kD + d4 * 4);
        float4 o;
        o.x = a.x / (1.f + __expf(-b.x));
        o.y = a.y / (1.f + __expf(-b.y));
        o.z = a.z / (1.f + __expf(-b.z));
        o.w = a.w / (1.f + __expf(-b.w));
        *(float4*)(g + (size_t)t * kD + d4 * 4) = o;
    }
}

// ================================================================ chunked attention
__global__ void __launch_bounds__(256)
attn_state_kernel(const float* __restrict__ y, float* __restrict__ state,
                  float* __restrict__ zs) {
    __shared__ float sK[64][36];
    __shared__ float sV[64][36];
    int t = blockIdx.x, h = blockIdx.y;
    int tid = threadIdx.x;
    int i4 = (tid & 7) * 4, rr = tid >> 3;
    #pragma unroll
    for (int rep = 0; rep < 2; rep++) {
        int s = rr + rep * 32;
        const float* base = y + (size_t)(t * 64 + s) * kQKV + h * 96;
        float4 kv = *(const float4*)(base + 32 + i4);
        float4 vv = *(const float4*)(base + 64 + i4);
        float4 ek = {__expf(kv.x), __expf(kv.y), __expf(kv.z), __expf(kv.w)};
        float4 ev = {__expf(vv.x), __expf(vv.y), __expf(vv.z), __expf(vv.w)};
        *(float4*)&sK[s][i4] = ek;
        *(float4*)&sV[s][i4] = ev;
    }
    __syncthreads();
    int i = tid >> 3, j0 = (tid & 7) * 4;
    float a0 = 0.f, a1 = 0.f, a2 = 0.f, a3 = 0.f;
    #pragma unroll 4
    for (int s = 0; s < 64; s++) {
        float k = sK[s][i];
        float4 v = *(float4*)&sV[s][j0];
        a0 += k * v.x; a1 += k * v.y; a2 += k * v.z; a3 += k * v.w;
    }
    float4 o = {a0, a1, a2, a3};
    *(float4*)&state[((size_t)(h * 16 + t) * 32 + i) * 32 + j0] = o;
    if (tid < 32) {
        float z = 0.f;
        #pragma unroll 4
        for (int s = 0; s < 64; s++) z += sK[s][tid];
        zs[(h * 16 + t) * 32 + tid] = z;
    }
}

// prefix over 16 tiles (prefetch then scan)
__global__ void __launch_bounds__(1024)
attn_prefix_kernel(float* __restrict__ state, float* __restrict__ zs) {
    int h = blockIdx.x;
    int idx = threadIdx.x;
    float v[16];
    #pragma unroll
    for (int t = 0; t < 16; t++)
        v[t] = state[(size_t)(h * 16 + t) * 1024 + idx];
    float run = 0.f;
    #pragma unroll
    for (int t = 0; t < 16; t++) {
        state[(size_t)(h * 16 + t) * 1024 + idx] = run;
        run += v[t];
    }
    if (idx < 32) {
        float zv[16];
        #pragma unroll
        for (int t = 0; t < 16; t++) zv[t] = zs[(h * 16 + t) * 32 + idx];
        float rz = 0.f;
        #pragma unroll
        for (int t = 0; t < 16; t++) {
            zs[(h * 16 + t) * 32 + idx] = rz;
            rz += zv[t];
        }
    }
}

__global__ void __launch_bounds__(256)
attn_out_kernel(const float* __restrict__ y, const float* __restrict__ state,
                const float* __restrict__ zs, float* __restrict__ att) {
    __shared__ float sQ[32][64];
    __shared__ float sK[32][64];
    __shared__ float sV[64][36];
    __shared__ float sSt[32][36];
    __shared__ float sZp[32];
    __shared__ float sP[64][65];
    __shared__ float sZ[64];

    int qt = blockIdx.x, h = blockIdx.y;
    int t0 = qt * 64;
    int tid = threadIdx.x;
    int i4 = (tid & 7) * 4, rr = tid >> 3;

    #pragma unroll
    for (int rep = 0; rep < 2; rep++) {
        int s = rr + rep * 32;
        const float* base = y + (size_t)(t0 + s) * kQKV + h * 96;
        float4 qv = *(const float4*)(base + i4);
        sQ[i4 + 0][s] = __expf(qv.x); sQ[i4 + 1][s] = __expf(qv.y);
        sQ[i4 + 2][s] = __expf(qv.z); sQ[i4 + 3][s] = __expf(qv.w);
        float4 kv = *(const float4*)(base + 32 + i4);
        sK[i4 + 0][s] = __expf(kv.x); sK[i4 + 1][s] = __expf(kv.y);
        sK[i4 + 2][s] = __expf(kv.z); sK[i4 + 3][s] = __expf(kv.w);
        float4 vv = *(const float4*)(base + 64 + i4);
        float4 ev = {__expf(vv.x), __expf(vv.y), __expf(vv.z), __expf(vv.w)};
        *(float4*)&sV[s][i4] = ev;
    }
    {
        int i = tid >> 3, j0 = (tid & 7) * 4;
        float4 st = *(const float4*)&state[((size_t)(h * 16 + qt) * 32 + i) * 32 + j0];
        *(float4*)&sSt[i][j0] = st;
        if (tid < 32) sZp[tid] = zs[(h * 16 + qt) * 32 + tid];
    }
    __syncthreads();

    int tk = tid & 15, tq = tid >> 4;
    {
        float p[4][4] = {};
        #pragma unroll
        for (int i = 0; i < 32; i++) {
            float4 a4 = *(float4*)&sQ[i][tq * 4];
            float4 b4 = *(float4*)&sK[i][tk * 4];
            float ar[4] = {a4.x, a4.y, a4.z, a4.w};
            float br[4] = {b4.x, b4.y, b4.z, b4.w};
            #pragma unroll
            for (int r = 0; r < 4; r++)
                #pragma unroll
                for (int c = 0; c < 4; c++)
                    p[r][c] += ar[r] * br[c];
        }
        #pragma unroll
        for (int r = 0; r < 4; r++)
            #pragma unroll
            for (int c = 0; c < 4; c++)
                sP[tq * 4 + r][tk * 4 + c] =
                    (tk * 4 + c > tq * 4 + r) ? 0.f : p[r][c];
    }
    __syncthreads();

    int vx = tid & 7, ry = tid >> 3;
    float Sacc[2][4] = {};
    float Zacc[2] = {};
    {
        #pragma unroll 4
        for (int i = 0; i < 32; i++) {
            float q0 = sQ[i][ry * 2 + 0];
            float q1 = sQ[i][ry * 2 + 1];
            float4 st = *(float4*)&sSt[i][vx * 4];
            Sacc[0][0] += q0 * st.x; Sacc[0][1] += q0 * st.y;
            Sacc[0][2] += q0 * st.z; Sacc[0][3] += q0 * st.w;
            Sacc[1][0] += q1 * st.x; Sacc[1][1] += q1 * st.y;
            Sacc[1][2] += q1 * st.z; Sacc[1][3] += q1 * st.w;
            if (vx == 0) {
                float z = sZp[i];
                Zacc[0] += q0 * z; Zacc[1] += q1 * z;
            }
        }
        #pragma unroll 8
        for (int s = 0; s < 64; s++) {
            float p0 = sP[ry * 2 + 0][s];
            float p1 = sP[ry * 2 + 1][s];
            float4 vv = *(float4*)&sV[s][vx * 4];
            Sacc[0][0] += p0 * vv.x; Sacc[0][1] += p0 * vv.y;
            Sacc[0][2] += p0 * vv.z; Sacc[0][3] += p0 * vv.w;
            Sacc[1][0] += p1 * vv.x; Sacc[1][1] += p1 * vv.y;
            Sacc[1][2] += p1 * vv.z; Sacc[1][3] += p1 * vv.w;
            if (vx == 0) { Zacc[0] += p0; Zacc[1] += p1; }
        }
    }
    if (vx == 0) { sZ[ry * 2] = Zacc[0]; sZ[ry * 2 + 1] = Zacc[1]; }
    __syncthreads();
    #pragma unroll
    for (int r = 0; r < 2; r++) {
        int row = t0 + ry * 2 + r;
        float lz = __logf(sZ[ry * 2 + r]);
        float4 o;
        o.x = __logf(Sacc[r][0]) - lz;
        o.y = __logf(Sacc[r][1]) - lz;
        o.z = __logf(Sacc[r][2]) - lz;
        o.w = __logf(Sacc[r][3]) - lz;
        *(float4*)&att[(size_t)row * kD + h * 32 + vx * 4] = o;
    }
}

// ================================================================ launch
extern "C" void kernel_launch(void* const* d_in, const int* in_sizes, int n_in,
                              void* d_out, int out_size) {
    const int*   tok     = (const int*)  d_in[0];
    const float* embed_w = (const float*)d_in[1];
    const float* pos_w   = (const float*)d_in[2];
    const float* pos_b   = (const float*)d_in[3];
    const float* ln1_g   = (const float*)d_in[4];
    const float* ln1_b   = (const float*)d_in[5];
    const float* qkv_w   = (const float*)d_in[6];
    const float* qkv_b   = (const float*)d_in[7];
    const float* ff_w1   = (const float*)d_in[8];
    const float* ff_b1   = (const float*)d_in[9];
    const float* ff_w2   = (const float*)d_in[10];
    const float* lnf_g   = (const float*)d_in[11];
    const float* lnf_b   = (const float*)d_in[12];
    float* out = (float*)d_out;

    float *x, *xn, *hbuf, *y, *att, *g, *st, *zsb;
    cudaGetSymbolAddress((void**)&x,    g_x);
    cudaGetSymbolAddress((void**)&xn,   g_xn);
    cudaGetSymbolAddress((void**)&hbuf, g_h);
    cudaGetSymbolAddress((void**)&y,    g_y);
    cudaGetSymbolAddress((void**)&att,  g_att);
    cudaGetSymbolAddress((void**)&g,    g_g);
    cudaGetSymbolAddress((void**)&st,   g_state);
    cudaGetSymbolAddress((void**)&zsb,  g_zs);

    cudaFuncSetAttribute(gemm_mma_kernel<false>,
                         cudaFuncAttributeMaxDynamicSharedMemorySize, kSmBytes);
    cudaFuncSetAttribute(gemm_mma_kernel<true>,
                         cudaFuncAttributeMaxDynamicSharedMemorySize, kSmBytes);

    // 1. embedding
    embed_kernel<<<(kS * 192 + 255) / 256, 256>>>(tok, embed_w, x);

    // 2. positional
    gemm_mma_kernel<false><<<dim3(kFF / 64, kS / 128), 256, kSmBytes>>>(
        x, pos_w, pos_b, nullptr, hbuf, kFF);
    pos_scan_kernel<<<6, 128>>>(hbuf, x);

    // 3. layers
    for (int l = 0; l < kL; l++) {
        ln_kernel<<<kS, 256>>>(x, ln1_g + (size_t)l * kD, ln1_b + (size_t)l * kD, xn);
        gemm_mma_kernel<false><<<dim3(kQKV / 64, kS / 128), 256, kSmBytes>>>(
            xn, qkv_w + (size_t)l * kD * kQKV, qkv_b + (size_t)l * kQKV, nullptr, y, kQKV);
        attn_state_kernel<<<dim3(16, kH), 256>>>(y, st, zsb);
        attn_prefix_kernel<<<kH, 1024>>>(st, zsb);
        attn_out_kernel<<<dim3(16, kH), 256>>>(y, st, zsb, att);
        gemm_mma_kernel<false><<<dim3(kFF / 64, kS / 128), 256, kSmBytes>>>(
            att, ff_w1 + (size_t)l * kD * kFF, ff_b1 + (size_t)l * kFF, nullptr, hbuf, kFF);
        glu_kernel<<<(kS * 192 + 255) / 256, 256>>>(hbuf, g);
        gemm_mma_kernel<false><<<dim3(kD / 64, kS / 128), 256, kSmBytes>>>(
            g, ff_w2 + (size_t)l * kD * kD, nullptr, x, x, kD);
    }

    // 4. final LN + logits
    ln_kernel<<<kS, 256>>>(x, lnf_g, lnf_b, xn);
    gemm_mma_kernel<true><<<dim3(kV / 64, kS / 128), 256, kSmBytes>>>(
        xn, embed_w, nullptr, nullptr, out, kV);
}